// round 3
// baseline (speedup 1.0000x reference)
#include <cuda_runtime.h>

#define BB 4
#define LL 2048
#define DD 1024
#define HH 16
#define DK 64

// Scratch buffers (allocation-free rule: __device__ globals)
__device__ float g_q[BB * LL * DD];
__device__ float g_k[BB * LL * DD];
__device__ float g_v[BB * LL * DD];
__device__ float g_ctx[BB * LL * DD];

// ============================================================
// GEMM: C[M,N] = A[M,K] @ W[N,K]^T + bias[N]
// A row-major [M,K], W row-major [N,K] (torch Linear weight layout)
// 128x128 tile, BK=8, 8x8 per thread, 256 threads
// ============================================================
#define GBM 128
#define GBN 128
#define GBK 8

__global__ __launch_bounds__(256)
void gemm_bias_kernel(const float* __restrict__ A,
                      const float* __restrict__ W,
                      const float* __restrict__ bias,
                      float* __restrict__ C,
                      int M, int N, int K) {
    __shared__ float As[GBK][GBM];
    __shared__ float Ws[GBK][GBN];

    const int tid = threadIdx.x;
    const int bm = blockIdx.y;
    const int bn = blockIdx.x;

    // load mapping: 256 threads load 128 rows x 8 k (one float4 each)
    const int lrow = tid >> 1;        // 0..127
    const int lk4  = (tid & 1) * 4;   // 0 or 4

    const float* Aptr = A + (size_t)(bm * GBM + lrow) * K + lk4;
    const float* Wptr = W + (size_t)(bn * GBN + lrow) * K + lk4;

    const int tx = tid & 15;   // 0..15  -> col group
    const int ty = tid >> 4;   // 0..15  -> row group

    float acc[8][8];
#pragma unroll
    for (int i = 0; i < 8; i++)
#pragma unroll
        for (int j = 0; j < 8; j++) acc[i][j] = 0.0f;

    for (int k0 = 0; k0 < K; k0 += GBK) {
        float4 a4 = *(const float4*)(Aptr + k0);
        float4 w4 = *(const float4*)(Wptr + k0);
        __syncthreads();  // previous iteration's reads done
        As[lk4 + 0][lrow] = a4.x;
        As[lk4 + 1][lrow] = a4.y;
        As[lk4 + 2][lrow] = a4.z;
        As[lk4 + 3][lrow] = a4.w;
        Ws[lk4 + 0][lrow] = w4.x;
        Ws[lk4 + 1][lrow] = w4.y;
        Ws[lk4 + 2][lrow] = w4.z;
        Ws[lk4 + 3][lrow] = w4.w;
        __syncthreads();

#pragma unroll
        for (int kk = 0; kk < GBK; kk++) {
            float4 ar0 = *(const float4*)&As[kk][ty * 8];
            float4 ar1 = *(const float4*)&As[kk][ty * 8 + 4];
            float4 br0 = *(const float4*)&Ws[kk][tx * 8];
            float4 br1 = *(const float4*)&Ws[kk][tx * 8 + 4];
            float ar[8] = {ar0.x, ar0.y, ar0.z, ar0.w, ar1.x, ar1.y, ar1.z, ar1.w};
            float br[8] = {br0.x, br0.y, br0.z, br0.w, br1.x, br1.y, br1.z, br1.w};
#pragma unroll
            for (int i = 0; i < 8; i++)
#pragma unroll
                for (int j = 0; j < 8; j++)
                    acc[i][j] = fmaf(ar[i], br[j], acc[i][j]);
        }
    }

    // epilogue: add bias, write out (float4)
    const int col0 = bn * GBN + tx * 8;
    float4 b0 = *(const float4*)&bias[col0];
    float4 b1 = *(const float4*)&bias[col0 + 4];
#pragma unroll
    for (int i = 0; i < 8; i++) {
        int row = bm * GBM + ty * 8 + i;
        float* cp = C + (size_t)row * N + col0;
        float4 o0, o1;
        o0.x = acc[i][0] + b0.x; o0.y = acc[i][1] + b0.y;
        o0.z = acc[i][2] + b0.z; o0.w = acc[i][3] + b0.w;
        o1.x = acc[i][4] + b1.x; o1.y = acc[i][5] + b1.y;
        o1.z = acc[i][6] + b1.z; o1.w = acc[i][7] + b1.w;
        *(float4*)cp = o0;
        *(float4*)(cp + 4) = o1;
    }
}

// ============================================================
// Causal flash attention, fp32.
// Q/K/V in [B, L, D] layout (head h occupies columns h*64..h*64+63).
// One thread per query row; 128 queries per block; 64-key tiles in smem.
// Online softmax in 8-key chunks (no S scratch needed).
// Output ctx written in [B, L, D] layout (no transpose needed).
// ============================================================
#define AQ 128
#define AK 64

__global__ __launch_bounds__(128)
void attn_kernel(const float* __restrict__ Q,
                 const float* __restrict__ K,
                 const float* __restrict__ V,
                 float* __restrict__ ctx) {
    __shared__ float Ks[AK][DK];
    __shared__ float Vs[AK][DK];

    const int tid = threadIdx.x;
    const int qt = blockIdx.x;
    const int h  = blockIdx.y;
    const int b  = blockIdx.z;

    const int q = qt * AQ + tid;
    const float scale = 0.125f;  // 1/sqrt(64)

    float qreg[DK];
    {
        const float* qptr = Q + ((size_t)(b * LL + q)) * DD + h * DK;
#pragma unroll
        for (int d4 = 0; d4 < DK / 4; d4++) {
            float4 v4 = *(const float4*)(qptr + d4 * 4);
            qreg[d4 * 4 + 0] = v4.x * scale;
            qreg[d4 * 4 + 1] = v4.y * scale;
            qreg[d4 * 4 + 2] = v4.z * scale;
            qreg[d4 * 4 + 3] = v4.w * scale;
        }
    }

    float o[DK];
#pragma unroll
    for (int d = 0; d < DK; d++) o[d] = 0.0f;
    float m = -1e30f, l = 0.0f;

    const int ntiles = 2 * qt + 2;  // keys up to qt*128+127 inclusive

    for (int t = 0; t < ntiles; t++) {
        const int k0 = t * AK;
        __syncthreads();  // previous tile's compute finished
        // load K,V tile: 64 rows x 16 float4 = 1024 float4 per tensor
        for (int i = tid; i < AK * (DK / 4); i += AQ) {
            int r = i >> 4;          // row 0..63
            int c4 = i & 15;         // float4 col
            size_t goff = ((size_t)(b * LL + k0 + r)) * DD + h * DK + c4 * 4;
            ((float4*)Ks[r])[c4] = *(const float4*)(K + goff);
            ((float4*)Vs[r])[c4] = *(const float4*)(V + goff);
        }
        __syncthreads();

        for (int jc = 0; jc < AK; jc += 8) {
            float sreg[8];
            float cmax = -1e30f;
#pragma unroll
            for (int jj = 0; jj < 8; jj++) {
                const int j = jc + jj;
                const float4* kr = (const float4*)Ks[j];
                float s = 0.0f;
#pragma unroll
                for (int d4 = 0; d4 < DK / 4; d4++) {
                    float4 kv = kr[d4];
                    s = fmaf(qreg[d4 * 4 + 0], kv.x, s);
                    s = fmaf(qreg[d4 * 4 + 1], kv.y, s);
                    s = fmaf(qreg[d4 * 4 + 2], kv.z, s);
                    s = fmaf(qreg[d4 * 4 + 3], kv.w, s);
                }
                if (k0 + j > q) s = -1e30f;  // causal mask
                sreg[jj] = s;
                cmax = fmaxf(cmax, s);
            }
            float mnew = fmaxf(m, cmax);
            float corr = __expf(m - mnew);
            l *= corr;
#pragma unroll
            for (int d = 0; d < DK; d++) o[d] *= corr;
            m = mnew;
#pragma unroll
            for (int jj = 0; jj < 8; jj++) {
                float p = __expf(sreg[jj] - mnew);
                l += p;
                const float4* vr = (const float4*)Vs[jc + jj];
#pragma unroll
                for (int d4 = 0; d4 < DK / 4; d4++) {
                    float4 vv = vr[d4];
                    o[d4 * 4 + 0] = fmaf(p, vv.x, o[d4 * 4 + 0]);
                    o[d4 * 4 + 1] = fmaf(p, vv.y, o[d4 * 4 + 1]);
                    o[d4 * 4 + 2] = fmaf(p, vv.z, o[d4 * 4 + 2]);
                    o[d4 * 4 + 3] = fmaf(p, vv.w, o[d4 * 4 + 3]);
                }
            }
        }
    }

    const float inv = 1.0f / l;
    float* op = ctx + ((size_t)(b * LL + q)) * DD + h * DK;
#pragma unroll
    for (int d4 = 0; d4 < DK / 4; d4++) {
        float4 v4;
        v4.x = o[d4 * 4 + 0] * inv;
        v4.y = o[d4 * 4 + 1] * inv;
        v4.z = o[d4 * 4 + 2] * inv;
        v4.w = o[d4 * 4 + 3] * inv;
        *(float4*)(op + d4 * 4) = v4;
    }
}

// ============================================================
// Launch
// ============================================================
extern "C" void kernel_launch(void* const* d_in, const int* in_sizes, int n_in,
                              void* d_out, int out_size) {
    const float* q    = (const float*)d_in[0];
    const float* k    = (const float*)d_in[1];
    const float* v    = (const float*)d_in[2];
    const float* wq_w = (const float*)d_in[3];
    const float* wq_b = (const float*)d_in[4];
    const float* wk_w = (const float*)d_in[5];
    const float* wk_b = (const float*)d_in[6];
    const float* wv_w = (const float*)d_in[7];
    const float* wv_b = (const float*)d_in[8];
    const float* wo_w = (const float*)d_in[9];
    const float* wo_b = (const float*)d_in[10];
    float* out = (float*)d_out;

    float *Qp, *Kp, *Vp, *Cp;
    cudaGetSymbolAddress((void**)&Qp, g_q);
    cudaGetSymbolAddress((void**)&Kp, g_k);
    cudaGetSymbolAddress((void**)&Vp, g_v);
    cudaGetSymbolAddress((void**)&Cp, g_ctx);

    const int M = BB * LL;  // 8192
    dim3 gg(DD / GBN, M / GBM);  // (8, 64)

    gemm_bias_kernel<<<gg, 256>>>(q, wq_w, wq_b, Qp, M, DD, DD);
    gemm_bias_kernel<<<gg, 256>>>(k, wk_w, wk_b, Kp, M, DD, DD);
    gemm_bias_kernel<<<gg, 256>>>(v, wv_w, wv_b, Vp, M, DD, DD);

    dim3 ga(LL / AQ, HH, BB);  // (16, 16, 4)
    attn_kernel<<<ga, AQ>>>(Qp, Kp, Vp, Cp);

    gemm_bias_kernel<<<gg, 256>>>(Cp, wo_w, wo_b, out, M, DD, DD);
}

// round 4
// speedup vs baseline: 1.2618x; 1.2618x over previous
#include <cuda_runtime.h>
#include <cstdint>

#define BB 4
#define LL 2048
#define DD 1024
#define HH 16
#define DK 64

// Scratch buffers (allocation-free rule: __device__ globals)
__device__ float g_q[BB * LL * DD];
__device__ float g_k[BB * LL * DD];
__device__ float g_v[BB * LL * DD];
__device__ float g_ctx[BB * LL * DD];

// ============================================================
// TF32 tensor-core GEMM: C[M,N] = A[M,K] @ W[N,K]^T + bias[N]
// mma.sync.aligned.m16n8k8.row.col.f32.tf32.tf32.f32
// Block tile 128x128x32, 8 warps (2x4), warp tile 64x32.
// ============================================================
#define BM 128
#define BN 128
#define BKT 32
#define SPAD 4
#define SSTR (BKT + SPAD)   // 36 words; 144B row stride (16B aligned, conflict-free frag loads)

__device__ __forceinline__ uint32_t f2tf(float x) {
    uint32_t u;
    asm("cvt.rna.tf32.f32 %0, %1;" : "=r"(u) : "f"(x));
    return u;
}

__device__ __forceinline__ void mma_tf32(float& d0, float& d1, float& d2, float& d3,
                                         uint32_t a0, uint32_t a1, uint32_t a2, uint32_t a3,
                                         uint32_t b0, uint32_t b1) {
    asm volatile(
        "mma.sync.aligned.m16n8k8.row.col.f32.tf32.tf32.f32 "
        "{%0,%1,%2,%3}, {%4,%5,%6,%7}, {%8,%9}, {%0,%1,%2,%3};"
        : "+f"(d0), "+f"(d1), "+f"(d2), "+f"(d3)
        : "r"(a0), "r"(a1), "r"(a2), "r"(a3), "r"(b0), "r"(b1));
}

__global__ __launch_bounds__(256)
void gemm_tf32_kernel(const float* __restrict__ A,
                      const float* __restrict__ W,
                      const float* __restrict__ bias,
                      float* __restrict__ C,
                      int M, int N, int K) {
    __shared__ float As[BM][SSTR];
    __shared__ float Ws[BN][SSTR];

    const int tid  = threadIdx.x;
    const int warp = tid >> 5;
    const int lane = tid & 31;
    const int wm = warp >> 2;   // 0..1  (64-row slab)
    const int wn = warp & 3;    // 0..3  (32-col slab)
    const int g  = lane >> 2;   // groupID 0..7
    const int t  = lane & 3;    // threadID_in_group 0..3

    const int bm = blockIdx.y;
    const int bn = blockIdx.x;

    float acc[4][4][4];
#pragma unroll
    for (int i = 0; i < 4; i++)
#pragma unroll
        for (int j = 0; j < 4; j++)
#pragma unroll
            for (int r = 0; r < 4; r++) acc[i][j][r] = 0.0f;

    // global load mapping: 128 rows x 8 float4 per tensor = 1024 float4; 4 per thread
    const int lrow = tid >> 1;  // unused; real mapping below

    for (int k0 = 0; k0 < K; k0 += BKT) {
        float4 av[4], wv[4];
#pragma unroll
        for (int j = 0; j < 4; j++) {
            int idx = tid + j * 256;
            int row = idx >> 3;
            int c4  = idx & 7;
            av[j] = *(const float4*)(A + (size_t)(bm * BM + row) * K + k0 + c4 * 4);
            wv[j] = *(const float4*)(W + (size_t)(bn * BN + row) * K + k0 + c4 * 4);
        }
        __syncthreads();   // previous iteration's fragment reads done
#pragma unroll
        for (int j = 0; j < 4; j++) {
            int idx = tid + j * 256;
            int row = idx >> 3;
            int c4  = idx & 7;
            float4 a = av[j], w = wv[j];
            float4 ac, wc;
            ac.x = __uint_as_float(f2tf(a.x)); ac.y = __uint_as_float(f2tf(a.y));
            ac.z = __uint_as_float(f2tf(a.z)); ac.w = __uint_as_float(f2tf(a.w));
            wc.x = __uint_as_float(f2tf(w.x)); wc.y = __uint_as_float(f2tf(w.y));
            wc.z = __uint_as_float(f2tf(w.z)); wc.w = __uint_as_float(f2tf(w.w));
            *(float4*)&As[row][c4 * 4] = ac;
            *(float4*)&Ws[row][c4 * 4] = wc;
        }
        __syncthreads();

#pragma unroll
        for (int ks = 0; ks < BKT / 8; ks++) {
            const int kk = ks * 8;
            uint32_t afr[4][4];
            uint32_t bfr[4][2];
#pragma unroll
            for (int mt = 0; mt < 4; mt++) {
                const int m0 = wm * 64 + mt * 16;
                afr[mt][0] = __float_as_uint(As[m0 + g][kk + t]);
                afr[mt][1] = __float_as_uint(As[m0 + g + 8][kk + t]);
                afr[mt][2] = __float_as_uint(As[m0 + g][kk + t + 4]);
                afr[mt][3] = __float_as_uint(As[m0 + g + 8][kk + t + 4]);
            }
#pragma unroll
            for (int nt = 0; nt < 4; nt++) {
                const int n0 = wn * 32 + nt * 8;
                bfr[nt][0] = __float_as_uint(Ws[n0 + g][kk + t]);
                bfr[nt][1] = __float_as_uint(Ws[n0 + g][kk + t + 4]);
            }
#pragma unroll
            for (int mt = 0; mt < 4; mt++)
#pragma unroll
                for (int nt = 0; nt < 4; nt++)
                    mma_tf32(acc[mt][nt][0], acc[mt][nt][1], acc[mt][nt][2], acc[mt][nt][3],
                             afr[mt][0], afr[mt][1], afr[mt][2], afr[mt][3],
                             bfr[nt][0], bfr[nt][1]);
        }
    }

    // epilogue: bias + store (float2 per c0/c1 pair)
#pragma unroll
    for (int mt = 0; mt < 4; mt++) {
        const int row0 = bm * BM + wm * 64 + mt * 16 + g;
#pragma unroll
        for (int nt = 0; nt < 4; nt++) {
            const int col = bn * BN + wn * 32 + nt * 8 + 2 * t;
            const float b0 = bias[col];
            const float b1 = bias[col + 1];
            float2 v0 = make_float2(acc[mt][nt][0] + b0, acc[mt][nt][1] + b1);
            float2 v1 = make_float2(acc[mt][nt][2] + b0, acc[mt][nt][3] + b1);
            *(float2*)(C + (size_t)row0 * N + col)       = v0;
            *(float2*)(C + (size_t)(row0 + 8) * N + col) = v1;
        }
    }
    (void)lrow;
}

// ============================================================
// Causal flash attention, fp32 (unchanged math; qt reversed so
// heavy blocks launch in the first wave → better load balance).
// ============================================================
#define AQ 128
#define AK 64

__global__ __launch_bounds__(128)
void attn_kernel(const float* __restrict__ Q,
                 const float* __restrict__ K,
                 const float* __restrict__ V,
                 float* __restrict__ ctx) {
    __shared__ float Ks[AK][DK];
    __shared__ float Vs[AK][DK];

    const int tid = threadIdx.x;
    const int qt = (int)gridDim.x - 1 - (int)blockIdx.x;  // heavy tiles first
    const int h  = blockIdx.y;
    const int b  = blockIdx.z;

    const int q = qt * AQ + tid;
    const float scale = 0.125f;  // 1/sqrt(64)

    float qreg[DK];
    {
        const float* qptr = Q + ((size_t)(b * LL + q)) * DD + h * DK;
#pragma unroll
        for (int d4 = 0; d4 < DK / 4; d4++) {
            float4 v4 = *(const float4*)(qptr + d4 * 4);
            qreg[d4 * 4 + 0] = v4.x * scale;
            qreg[d4 * 4 + 1] = v4.y * scale;
            qreg[d4 * 4 + 2] = v4.z * scale;
            qreg[d4 * 4 + 3] = v4.w * scale;
        }
    }

    float o[DK];
#pragma unroll
    for (int d = 0; d < DK; d++) o[d] = 0.0f;
    float m = -1e30f, l = 0.0f;

    const int ntiles = 2 * qt + 2;

    for (int tt = 0; tt < ntiles; tt++) {
        const int k0 = tt * AK;
        __syncthreads();
        for (int i = tid; i < AK * (DK / 4); i += AQ) {
            int r = i >> 4;
            int c4 = i & 15;
            size_t goff = ((size_t)(b * LL + k0 + r)) * DD + h * DK + c4 * 4;
            ((float4*)Ks[r])[c4] = *(const float4*)(K + goff);
            ((float4*)Vs[r])[c4] = *(const float4*)(V + goff);
        }
        __syncthreads();

        for (int jc = 0; jc < AK; jc += 8) {
            float sreg[8];
            float cmax = -1e30f;
#pragma unroll
            for (int jj = 0; jj < 8; jj++) {
                const int j = jc + jj;
                const float4* kr = (const float4*)Ks[j];
                float s = 0.0f;
#pragma unroll
                for (int d4 = 0; d4 < DK / 4; d4++) {
                    float4 kv = kr[d4];
                    s = fmaf(qreg[d4 * 4 + 0], kv.x, s);
                    s = fmaf(qreg[d4 * 4 + 1], kv.y, s);
                    s = fmaf(qreg[d4 * 4 + 2], kv.z, s);
                    s = fmaf(qreg[d4 * 4 + 3], kv.w, s);
                }
                if (k0 + j > q) s = -1e30f;
                sreg[jj] = s;
                cmax = fmaxf(cmax, s);
            }
            float mnew = fmaxf(m, cmax);
            float corr = __expf(m - mnew);
            l *= corr;
#pragma unroll
            for (int d = 0; d < DK; d++) o[d] *= corr;
            m = mnew;
#pragma unroll
            for (int jj = 0; jj < 8; jj++) {
                float p = __expf(sreg[jj] - mnew);
                l += p;
                const float4* vr = (const float4*)Vs[jc + jj];
#pragma unroll
                for (int d4 = 0; d4 < DK / 4; d4++) {
                    float4 vv = vr[d4];
                    o[d4 * 4 + 0] = fmaf(p, vv.x, o[d4 * 4 + 0]);
                    o[d4 * 4 + 1] = fmaf(p, vv.y, o[d4 * 4 + 1]);
                    o[d4 * 4 + 2] = fmaf(p, vv.z, o[d4 * 4 + 2]);
                    o[d4 * 4 + 3] = fmaf(p, vv.w, o[d4 * 4 + 3]);
                }
            }
        }
    }

    const float inv = 1.0f / l;
    float* op = ctx + ((size_t)(b * LL + q)) * DD + h * DK;
#pragma unroll
    for (int d4 = 0; d4 < DK / 4; d4++) {
        float4 v4;
        v4.x = o[d4 * 4 + 0] * inv;
        v4.y = o[d4 * 4 + 1] * inv;
        v4.z = o[d4 * 4 + 2] * inv;
        v4.w = o[d4 * 4 + 3] * inv;
        *(float4*)(op + d4 * 4) = v4;
    }
}

// ============================================================
// Launch
// ============================================================
extern "C" void kernel_launch(void* const* d_in, const int* in_sizes, int n_in,
                              void* d_out, int out_size) {
    const float* q    = (const float*)d_in[0];
    const float* k    = (const float*)d_in[1];
    const float* v    = (const float*)d_in[2];
    const float* wq_w = (const float*)d_in[3];
    const float* wq_b = (const float*)d_in[4];
    const float* wk_w = (const float*)d_in[5];
    const float* wk_b = (const float*)d_in[6];
    const float* wv_w = (const float*)d_in[7];
    const float* wv_b = (const float*)d_in[8];
    const float* wo_w = (const float*)d_in[9];
    const float* wo_b = (const float*)d_in[10];
    float* out = (float*)d_out;

    float *Qp, *Kp, *Vp, *Cp;
    cudaGetSymbolAddress((void**)&Qp, g_q);
    cudaGetSymbolAddress((void**)&Kp, g_k);
    cudaGetSymbolAddress((void**)&Vp, g_v);
    cudaGetSymbolAddress((void**)&Cp, g_ctx);

    const int M = BB * LL;  // 8192
    dim3 gg(DD / BN, M / BM);  // (8, 64)

    gemm_tf32_kernel<<<gg, 256>>>(q, wq_w, wq_b, Qp, M, DD, DD);
    gemm_tf32_kernel<<<gg, 256>>>(k, wk_w, wk_b, Kp, M, DD, DD);
    gemm_tf32_kernel<<<gg, 256>>>(v, wv_w, wv_b, Vp, M, DD, DD);

    dim3 ga(LL / AQ, HH, BB);  // (16, 16, 4)
    attn_kernel<<<ga, AQ>>>(Qp, Kp, Vp, Cp);

    gemm_tf32_kernel<<<gg, 256>>>(Cp, wo_w, wo_b, out, M, DD, DD);
}

// round 5
// speedup vs baseline: 2.5605x; 2.0292x over previous
#include <cuda_runtime.h>
#include <cstdint>

#define BB 4
#define LL 2048
#define DD 1024
#define HH 16
#define DK 64

// Scratch buffers (allocation-free rule: __device__ globals)
__device__ float g_q[BB * LL * DD];
__device__ float g_k[BB * LL * DD];
__device__ float g_v[BB * LL * DD];
__device__ float g_ctx[BB * LL * DD];

__device__ __forceinline__ uint32_t f2tf(float x) {
    uint32_t u;
    asm("cvt.rna.tf32.f32 %0, %1;" : "=r"(u) : "f"(x));
    return u;
}

__device__ __forceinline__ void mma_tf32(float& d0, float& d1, float& d2, float& d3,
                                         uint32_t a0, uint32_t a1, uint32_t a2, uint32_t a3,
                                         uint32_t b0, uint32_t b1) {
    asm volatile(
        "mma.sync.aligned.m16n8k8.row.col.f32.tf32.tf32.f32 "
        "{%0,%1,%2,%3}, {%4,%5,%6,%7}, {%8,%9}, {%0,%1,%2,%3};"
        : "+f"(d0), "+f"(d1), "+f"(d2), "+f"(d3)
        : "r"(a0), "r"(a1), "r"(a2), "r"(a3), "r"(b0), "r"(b1));
}

// ============================================================
// TF32 tensor-core GEMM: C[M,N] = A[M,K] @ W[N,K]^T + bias[N]
// ============================================================
#define BM 128
#define BN 128
#define BKT 32
#define SPAD 4
#define SSTR (BKT + SPAD)

__global__ __launch_bounds__(256)
void gemm_tf32_kernel(const float* __restrict__ A,
                      const float* __restrict__ W,
                      const float* __restrict__ bias,
                      float* __restrict__ C,
                      int M, int N, int K) {
    __shared__ float As[BM][SSTR];
    __shared__ float Ws[BN][SSTR];

    const int tid  = threadIdx.x;
    const int warp = tid >> 5;
    const int lane = tid & 31;
    const int wm = warp >> 2;
    const int wn = warp & 3;
    const int g  = lane >> 2;
    const int t  = lane & 3;

    const int bm = blockIdx.y;
    const int bn = blockIdx.x;

    float acc[4][4][4];
#pragma unroll
    for (int i = 0; i < 4; i++)
#pragma unroll
        for (int j = 0; j < 4; j++)
#pragma unroll
            for (int r = 0; r < 4; r++) acc[i][j][r] = 0.0f;

    for (int k0 = 0; k0 < K; k0 += BKT) {
        float4 av[4], wv[4];
#pragma unroll
        for (int j = 0; j < 4; j++) {
            int idx = tid + j * 256;
            int row = idx >> 3;
            int c4  = idx & 7;
            av[j] = *(const float4*)(A + (size_t)(bm * BM + row) * K + k0 + c4 * 4);
            wv[j] = *(const float4*)(W + (size_t)(bn * BN + row) * K + k0 + c4 * 4);
        }
        __syncthreads();
#pragma unroll
        for (int j = 0; j < 4; j++) {
            int idx = tid + j * 256;
            int row = idx >> 3;
            int c4  = idx & 7;
            float4 a = av[j], w = wv[j];
            float4 ac, wc;
            ac.x = __uint_as_float(f2tf(a.x)); ac.y = __uint_as_float(f2tf(a.y));
            ac.z = __uint_as_float(f2tf(a.z)); ac.w = __uint_as_float(f2tf(a.w));
            wc.x = __uint_as_float(f2tf(w.x)); wc.y = __uint_as_float(f2tf(w.y));
            wc.z = __uint_as_float(f2tf(w.z)); wc.w = __uint_as_float(f2tf(w.w));
            *(float4*)&As[row][c4 * 4] = ac;
            *(float4*)&Ws[row][c4 * 4] = wc;
        }
        __syncthreads();

#pragma unroll
        for (int ks = 0; ks < BKT / 8; ks++) {
            const int kk = ks * 8;
            uint32_t afr[4][4];
            uint32_t bfr[4][2];
#pragma unroll
            for (int mt = 0; mt < 4; mt++) {
                const int m0 = wm * 64 + mt * 16;
                afr[mt][0] = __float_as_uint(As[m0 + g][kk + t]);
                afr[mt][1] = __float_as_uint(As[m0 + g + 8][kk + t]);
                afr[mt][2] = __float_as_uint(As[m0 + g][kk + t + 4]);
                afr[mt][3] = __float_as_uint(As[m0 + g + 8][kk + t + 4]);
            }
#pragma unroll
            for (int nt = 0; nt < 4; nt++) {
                const int n0 = wn * 32 + nt * 8;
                bfr[nt][0] = __float_as_uint(Ws[n0 + g][kk + t]);
                bfr[nt][1] = __float_as_uint(Ws[n0 + g][kk + t + 4]);
            }
#pragma unroll
            for (int mt = 0; mt < 4; mt++)
#pragma unroll
                for (int nt = 0; nt < 4; nt++)
                    mma_tf32(acc[mt][nt][0], acc[mt][nt][1], acc[mt][nt][2], acc[mt][nt][3],
                             afr[mt][0], afr[mt][1], afr[mt][2], afr[mt][3],
                             bfr[nt][0], bfr[nt][1]);
        }
    }

#pragma unroll
    for (int mt = 0; mt < 4; mt++) {
        const int row0 = bm * BM + wm * 64 + mt * 16 + g;
#pragma unroll
        for (int nt = 0; nt < 4; nt++) {
            const int col = bn * BN + wn * 32 + nt * 8 + 2 * t;
            const float b0 = bias[col];
            const float b1 = bias[col + 1];
            float2 v0 = make_float2(acc[mt][nt][0] + b0, acc[mt][nt][1] + b1);
            float2 v1 = make_float2(acc[mt][nt][2] + b0, acc[mt][nt][3] + b1);
            *(float2*)(C + (size_t)row0 * N + col)       = v0;
            *(float2*)(C + (size_t)(row0 + 8) * N + col) = v1;
        }
    }
}

// ============================================================
// Tensor-core causal flash attention (tf32 mma).
// Block: 128 queries, 8 warps x 16 rows. 64-key tiles in smem.
// Q fragments in registers; online softmax on mma c-fragments;
// P->A-fragment transpose via intra-quad shuffles.
// ============================================================
#define KSTR 68   // Ks word stride: 4g+t covers all banks
#define VSTR 72   // Vs word stride: 8t+g covers all banks

__global__ __launch_bounds__(256, 2)
void attn_mma_kernel(const float* __restrict__ Q,
                     const float* __restrict__ K,
                     const float* __restrict__ V,
                     float* __restrict__ ctx) {
    __shared__ float Ks[64][KSTR];
    __shared__ float Vs[64][VSTR];

    const int tid  = threadIdx.x;
    const int warp = tid >> 5;
    const int lane = tid & 31;
    const int g = lane >> 2;
    const int t = lane & 3;

    const int qt = (int)gridDim.x - 1 - (int)blockIdx.x;  // heavy tiles first
    const int h  = blockIdx.y;
    const int b  = blockIdx.z;

    const int q0   = qt * 128;
    const int rowA = q0 + warp * 16 + g;
    const int rowB = rowA + 8;

    // Q fragments (scaled by 1/sqrt(DK), converted to tf32), resident all loop
    uint32_t qa[8][4];
    {
        const float* qA = Q + (size_t)(b * LL + rowA) * DD + h * DK;
        const float* qB = Q + (size_t)(b * LL + rowB) * DD + h * DK;
#pragma unroll
        for (int ks = 0; ks < 8; ks++) {
            qa[ks][0] = f2tf(qA[ks * 8 + t] * 0.125f);
            qa[ks][1] = f2tf(qB[ks * 8 + t] * 0.125f);
            qa[ks][2] = f2tf(qA[ks * 8 + t + 4] * 0.125f);
            qa[ks][3] = f2tf(qB[ks * 8 + t + 4] * 0.125f);
        }
    }

    float o[8][4];
#pragma unroll
    for (int nd = 0; nd < 8; nd++)
#pragma unroll
        for (int r = 0; r < 4; r++) o[nd][r] = 0.0f;
    float m0 = -1e30f, m1 = -1e30f, l0 = 0.0f, l1 = 0.0f;

    const int ntiles = 2 * qt + 2;

    for (int tt = 0; tt < ntiles; tt++) {
        const int k0 = tt * 64;
        __syncthreads();
        // cooperative K/V tile load, cvt to tf32 at store
        for (int i = tid; i < 64 * 16; i += 256) {
            int r  = i >> 4;
            int c4 = i & 15;
            size_t goff = (size_t)(b * LL + k0 + r) * DD + h * DK + c4 * 4;
            float4 kv = *(const float4*)(K + goff);
            float4 vv = *(const float4*)(V + goff);
            float4 kc, vc;
            kc.x = __uint_as_float(f2tf(kv.x)); kc.y = __uint_as_float(f2tf(kv.y));
            kc.z = __uint_as_float(f2tf(kv.z)); kc.w = __uint_as_float(f2tf(kv.w));
            vc.x = __uint_as_float(f2tf(vv.x)); vc.y = __uint_as_float(f2tf(vv.y));
            vc.z = __uint_as_float(f2tf(vv.z)); vc.w = __uint_as_float(f2tf(vv.w));
            *(float4*)&Ks[r][c4 * 4] = kc;
            *(float4*)&Vs[r][c4 * 4] = vc;
        }
        __syncthreads();

        // S = Q K^T  (16x64 per warp)
        float s[8][4];
#pragma unroll
        for (int nt = 0; nt < 8; nt++)
#pragma unroll
            for (int r = 0; r < 4; r++) s[nt][r] = 0.0f;

#pragma unroll
        for (int ks = 0; ks < 8; ks++) {
            const int kk = ks * 8;
#pragma unroll
            for (int nt = 0; nt < 8; nt++) {
                uint32_t b0 = __float_as_uint(Ks[nt * 8 + g][kk + t]);
                uint32_t b1 = __float_as_uint(Ks[nt * 8 + g][kk + t + 4]);
                mma_tf32(s[nt][0], s[nt][1], s[nt][2], s[nt][3],
                         qa[ks][0], qa[ks][1], qa[ks][2], qa[ks][3], b0, b1);
            }
        }

        // causal mask on diagonal tiles only (last two)
        if (tt >= 2 * qt) {
#pragma unroll
            for (int nt = 0; nt < 8; nt++) {
                int col = k0 + nt * 8 + 2 * t;
                if (col     > rowA) s[nt][0] = -1e30f;
                if (col + 1 > rowA) s[nt][1] = -1e30f;
                if (col     > rowB) s[nt][2] = -1e30f;
                if (col + 1 > rowB) s[nt][3] = -1e30f;
            }
        }

        // row max across 64 cols: local regs + butterfly over t-lanes
        float mx0 = -1e30f, mx1 = -1e30f;
#pragma unroll
        for (int nt = 0; nt < 8; nt++) {
            mx0 = fmaxf(mx0, fmaxf(s[nt][0], s[nt][1]));
            mx1 = fmaxf(mx1, fmaxf(s[nt][2], s[nt][3]));
        }
        mx0 = fmaxf(mx0, __shfl_xor_sync(0xffffffffu, mx0, 1));
        mx0 = fmaxf(mx0, __shfl_xor_sync(0xffffffffu, mx0, 2));
        mx1 = fmaxf(mx1, __shfl_xor_sync(0xffffffffu, mx1, 1));
        mx1 = fmaxf(mx1, __shfl_xor_sync(0xffffffffu, mx1, 2));

        float mn0 = fmaxf(m0, mx0), mn1 = fmaxf(m1, mx1);
        float cr0 = __expf(m0 - mn0), cr1 = __expf(m1 - mn1);
        m0 = mn0; m1 = mn1;
        l0 *= cr0; l1 *= cr1;
#pragma unroll
        for (int nd = 0; nd < 8; nd++) {
            o[nd][0] *= cr0; o[nd][1] *= cr0;
            o[nd][2] *= cr1; o[nd][3] *= cr1;
        }

        float s0 = 0.0f, s1 = 0.0f;
#pragma unroll
        for (int nt = 0; nt < 8; nt++) {
            s[nt][0] = __expf(s[nt][0] - mn0);
            s[nt][1] = __expf(s[nt][1] - mn0);
            s[nt][2] = __expf(s[nt][2] - mn1);
            s[nt][3] = __expf(s[nt][3] - mn1);
            s0 += s[nt][0] + s[nt][1];
            s1 += s[nt][2] + s[nt][3];
        }
        s0 += __shfl_xor_sync(0xffffffffu, s0, 1);
        s0 += __shfl_xor_sync(0xffffffffu, s0, 2);
        s1 += __shfl_xor_sync(0xffffffffu, s1, 1);
        s1 += __shfl_xor_sync(0xffffffffu, s1, 2);
        l0 += s0; l1 += s1;

        // O += P V : transpose P c-frags -> a-frags via intra-quad shuffles
        const int src1 = (lane & 28) | (t >> 1);
#pragma unroll
        for (int ks = 0; ks < 8; ks++) {
            uint32_t u0 = f2tf(s[ks][0]), u1 = f2tf(s[ks][1]);
            uint32_t u2 = f2tf(s[ks][2]), u3 = f2tf(s[ks][3]);
            uint32_t x0 = __shfl_sync(0xffffffffu, u0, src1);
            uint32_t x1 = __shfl_sync(0xffffffffu, u1, src1);
            uint32_t x2 = __shfl_sync(0xffffffffu, u2, src1);
            uint32_t x3 = __shfl_sync(0xffffffffu, u3, src1);
            uint32_t y0 = __shfl_sync(0xffffffffu, u0, src1 + 2);
            uint32_t y1 = __shfl_sync(0xffffffffu, u1, src1 + 2);
            uint32_t y2 = __shfl_sync(0xffffffffu, u2, src1 + 2);
            uint32_t y3 = __shfl_sync(0xffffffffu, u3, src1 + 2);
            uint32_t a0 = (t & 1) ? x1 : x0;
            uint32_t a1 = (t & 1) ? x3 : x2;
            uint32_t a2 = (t & 1) ? y1 : y0;
            uint32_t a3 = (t & 1) ? y3 : y2;
#pragma unroll
            for (int nd = 0; nd < 8; nd++) {
                uint32_t b0 = __float_as_uint(Vs[ks * 8 + t][nd * 8 + g]);
                uint32_t b1 = __float_as_uint(Vs[ks * 8 + t + 4][nd * 8 + g]);
                mma_tf32(o[nd][0], o[nd][1], o[nd][2], o[nd][3],
                         a0, a1, a2, a3, b0, b1);
            }
        }
    }

    const float i0 = 1.0f / l0, i1 = 1.0f / l1;
#pragma unroll
    for (int nd = 0; nd < 8; nd++) {
        const int col = h * DK + nd * 8 + 2 * t;
        float2 vA = make_float2(o[nd][0] * i0, o[nd][1] * i0);
        float2 vB = make_float2(o[nd][2] * i1, o[nd][3] * i1);
        *(float2*)(ctx + (size_t)(b * LL + rowA) * DD + col) = vA;
        *(float2*)(ctx + (size_t)(b * LL + rowB) * DD + col) = vB;
    }
}

// ============================================================
// Launch
// ============================================================
extern "C" void kernel_launch(void* const* d_in, const int* in_sizes, int n_in,
                              void* d_out, int out_size) {
    const float* q    = (const float*)d_in[0];
    const float* k    = (const float*)d_in[1];
    const float* v    = (const float*)d_in[2];
    const float* wq_w = (const float*)d_in[3];
    const float* wq_b = (const float*)d_in[4];
    const float* wk_w = (const float*)d_in[5];
    const float* wk_b = (const float*)d_in[6];
    const float* wv_w = (const float*)d_in[7];
    const float* wv_b = (const float*)d_in[8];
    const float* wo_w = (const float*)d_in[9];
    const float* wo_b = (const float*)d_in[10];
    float* out = (float*)d_out;

    float *Qp, *Kp, *Vp, *Cp;
    cudaGetSymbolAddress((void**)&Qp, g_q);
    cudaGetSymbolAddress((void**)&Kp, g_k);
    cudaGetSymbolAddress((void**)&Vp, g_v);
    cudaGetSymbolAddress((void**)&Cp, g_ctx);

    const int M = BB * LL;  // 8192
    dim3 gg(DD / BN, M / BM);  // (8, 64)

    gemm_tf32_kernel<<<gg, 256>>>(q, wq_w, wq_b, Qp, M, DD, DD);
    gemm_tf32_kernel<<<gg, 256>>>(k, wk_w, wk_b, Kp, M, DD, DD);
    gemm_tf32_kernel<<<gg, 256>>>(v, wv_w, wv_b, Vp, M, DD, DD);

    dim3 ga(LL / 128, HH, BB);  // (16, 16, 4)
    attn_mma_kernel<<<ga, 256>>>(Qp, Kp, Vp, Cp);

    gemm_tf32_kernel<<<gg, 256>>>(Cp, wo_w, wo_b, out, M, DD, DD);
}

// round 7
// speedup vs baseline: 2.6699x; 1.0427x over previous
#include <cuda_runtime.h>
#include <cstdint>

#define BB 4
#define LL 2048
#define DD 1024
#define HH 16
#define DK 64

// Scratch buffers (allocation-free rule: __device__ globals)
__device__ float g_q[BB * LL * DD];
__device__ float g_k[BB * LL * DD];
__device__ float g_v[BB * LL * DD];
__device__ float g_ctx[BB * LL * DD];

__device__ __forceinline__ uint32_t f2tf(float x) {
    uint32_t u;
    asm("cvt.rna.tf32.f32 %0, %1;" : "=r"(u) : "f"(x));
    return u;
}

__device__ __forceinline__ void mma_tf32(float& d0, float& d1, float& d2, float& d3,
                                         uint32_t a0, uint32_t a1, uint32_t a2, uint32_t a3,
                                         uint32_t b0, uint32_t b1) {
    asm volatile(
        "mma.sync.aligned.m16n8k8.row.col.f32.tf32.tf32.f32 "
        "{%0,%1,%2,%3}, {%4,%5,%6,%7}, {%8,%9}, {%0,%1,%2,%3};"
        : "+f"(d0), "+f"(d1), "+f"(d2), "+f"(d3)
        : "r"(a0), "r"(a1), "r"(a2), "r"(a3), "r"(b0), "r"(b1));
}

// ============================================================
// TF32 tensor-core GEMM: C[M,N] = A[M,K] @ W[N,K]^T + bias[N]
// Software-pipelined: next k-tile prefetched into registers
// while current tile's 64 MMAs execute.
// ============================================================
#define BM 128
#define BN 128
#define BKT 32
#define SPAD 4
#define SSTR (BKT + SPAD)

struct GemmArgs {
    const float* A;
    const float* W;
    const float* bias;
    float* C;
};

__device__ __forceinline__
void gemm_tile_body(const float* __restrict__ A,
                    const float* __restrict__ W,
                    const float* __restrict__ bias,
                    float* __restrict__ C,
                    int M, int N, int K, int bm, int bn,
                    float As[BM][SSTR], float Ws[BN][SSTR]) {
    const int tid  = threadIdx.x;
    const int warp = tid >> 5;
    const int lane = tid & 31;
    const int wm = warp >> 2;
    const int wn = warp & 3;
    const int g  = lane >> 2;
    const int t  = lane & 3;

    float acc[4][4][4];
#pragma unroll
    for (int i = 0; i < 4; i++)
#pragma unroll
        for (int j = 0; j < 4; j++)
#pragma unroll
            for (int r = 0; r < 4; r++) acc[i][j][r] = 0.0f;

    // per-thread load coords (row = idx>>3, c4 = idx&7 over idx = tid + j*256)
    float4 av[4], wv[4];
#pragma unroll
    for (int j = 0; j < 4; j++) {
        int idx = tid + j * 256;
        int row = idx >> 3;
        int c4  = idx & 7;
        av[j] = *(const float4*)(A + (size_t)(bm * BM + row) * K + c4 * 4);
        wv[j] = *(const float4*)(W + (size_t)(bn * BN + row) * K + c4 * 4);
    }

    for (int k0 = 0; k0 < K; k0 += BKT) {
        __syncthreads();   // previous iteration's fragment reads done
#pragma unroll
        for (int j = 0; j < 4; j++) {
            int idx = tid + j * 256;
            int row = idx >> 3;
            int c4  = idx & 7;
            float4 a = av[j], w = wv[j];
            float4 ac, wc;
            ac.x = __uint_as_float(f2tf(a.x)); ac.y = __uint_as_float(f2tf(a.y));
            ac.z = __uint_as_float(f2tf(a.z)); ac.w = __uint_as_float(f2tf(a.w));
            wc.x = __uint_as_float(f2tf(w.x)); wc.y = __uint_as_float(f2tf(w.y));
            wc.z = __uint_as_float(f2tf(w.z)); wc.w = __uint_as_float(f2tf(w.w));
            *(float4*)&As[row][c4 * 4] = ac;
            *(float4*)&Ws[row][c4 * 4] = wc;
        }
        __syncthreads();

        // prefetch NEXT tile (overlaps with MMA below)
        if (k0 + BKT < K) {
#pragma unroll
            for (int j = 0; j < 4; j++) {
                int idx = tid + j * 256;
                int row = idx >> 3;
                int c4  = idx & 7;
                av[j] = *(const float4*)(A + (size_t)(bm * BM + row) * K + (k0 + BKT) + c4 * 4);
                wv[j] = *(const float4*)(W + (size_t)(bn * BN + row) * K + (k0 + BKT) + c4 * 4);
            }
        }

#pragma unroll
        for (int ks = 0; ks < BKT / 8; ks++) {
            const int kk = ks * 8;
            uint32_t afr[4][4];
            uint32_t bfr[4][2];
#pragma unroll
            for (int mt = 0; mt < 4; mt++) {
                const int m0 = wm * 64 + mt * 16;
                afr[mt][0] = __float_as_uint(As[m0 + g][kk + t]);
                afr[mt][1] = __float_as_uint(As[m0 + g + 8][kk + t]);
                afr[mt][2] = __float_as_uint(As[m0 + g][kk + t + 4]);
                afr[mt][3] = __float_as_uint(As[m0 + g + 8][kk + t + 4]);
            }
#pragma unroll
            for (int nt = 0; nt < 4; nt++) {
                const int n0 = wn * 32 + nt * 8;
                bfr[nt][0] = __float_as_uint(Ws[n0 + g][kk + t]);
                bfr[nt][1] = __float_as_uint(Ws[n0 + g][kk + t + 4]);
            }
#pragma unroll
            for (int mt = 0; mt < 4; mt++)
#pragma unroll
                for (int nt = 0; nt < 4; nt++)
                    mma_tf32(acc[mt][nt][0], acc[mt][nt][1], acc[mt][nt][2], acc[mt][nt][3],
                             afr[mt][0], afr[mt][1], afr[mt][2], afr[mt][3],
                             bfr[nt][0], bfr[nt][1]);
        }
    }

#pragma unroll
    for (int mt = 0; mt < 4; mt++) {
        const int row0 = bm * BM + wm * 64 + mt * 16 + g;
#pragma unroll
        for (int nt = 0; nt < 4; nt++) {
            const int col = bn * BN + wn * 32 + nt * 8 + 2 * t;
            const float b0 = bias[col];
            const float b1 = bias[col + 1];
            float2 v0 = make_float2(acc[mt][nt][0] + b0, acc[mt][nt][1] + b1);
            float2 v1 = make_float2(acc[mt][nt][2] + b0, acc[mt][nt][3] + b1);
            *(float2*)(C + (size_t)row0 * N + col)       = v0;
            *(float2*)(C + (size_t)(row0 + 8) * N + col) = v1;
        }
    }
}

// Fused Q/K/V projections: blockIdx.z selects the (A, W, bias, C) triplet.
__global__ __launch_bounds__(256)
void gemm_qkv_kernel(GemmArgs a0, GemmArgs a1, GemmArgs a2, int M, int N, int K) {
    __shared__ float As[BM][SSTR];
    __shared__ float Ws[BN][SSTR];
    GemmArgs ga = (blockIdx.z == 0) ? a0 : (blockIdx.z == 1) ? a1 : a2;
    gemm_tile_body(ga.A, ga.W, ga.bias, ga.C, M, N, K,
                   blockIdx.y, blockIdx.x, As, Ws);
}

__global__ __launch_bounds__(256)
void gemm_tf32_kernel(const float* __restrict__ A,
                      const float* __restrict__ W,
                      const float* __restrict__ bias,
                      float* __restrict__ C,
                      int M, int N, int K) {
    __shared__ float As[BM][SSTR];
    __shared__ float Ws[BN][SSTR];
    gemm_tile_body(A, W, bias, C, M, N, K, blockIdx.y, blockIdx.x, As, Ws);
}

// ============================================================
// Tensor-core causal flash attention (tf32 mma). Unchanged from R4.
// ============================================================
#define KSTR 68
#define VSTR 72

__global__ __launch_bounds__(256, 2)
void attn_mma_kernel(const float* __restrict__ Q,
                     const float* __restrict__ K,
                     const float* __restrict__ V,
                     float* __restrict__ ctx) {
    __shared__ float Ks[64][KSTR];
    __shared__ float Vs[64][VSTR];

    const int tid  = threadIdx.x;
    const int warp = tid >> 5;
    const int lane = tid & 31;
    const int g = lane >> 2;
    const int t = lane & 3;

    const int qt = (int)gridDim.x - 1 - (int)blockIdx.x;
    const int h  = blockIdx.y;
    const int b  = blockIdx.z;

    const int q0   = qt * 128;
    const int rowA = q0 + warp * 16 + g;
    const int rowB = rowA + 8;

    uint32_t qa[8][4];
    {
        const float* qA = Q + (size_t)(b * LL + rowA) * DD + h * DK;
        const float* qB = Q + (size_t)(b * LL + rowB) * DD + h * DK;
#pragma unroll
        for (int ks = 0; ks < 8; ks++) {
            qa[ks][0] = f2tf(qA[ks * 8 + t] * 0.125f);
            qa[ks][1] = f2tf(qB[ks * 8 + t] * 0.125f);
            qa[ks][2] = f2tf(qA[ks * 8 + t + 4] * 0.125f);
            qa[ks][3] = f2tf(qB[ks * 8 + t + 4] * 0.125f);
        }
    }

    float o[8][4];
#pragma unroll
    for (int nd = 0; nd < 8; nd++)
#pragma unroll
        for (int r = 0; r < 4; r++) o[nd][r] = 0.0f;
    float m0 = -1e30f, m1 = -1e30f, l0 = 0.0f, l1 = 0.0f;

    const int ntiles = 2 * qt + 2;

    for (int tt = 0; tt < ntiles; tt++) {
        const int k0 = tt * 64;
        __syncthreads();
        for (int i = tid; i < 64 * 16; i += 256) {
            int r  = i >> 4;
            int c4 = i & 15;
            size_t goff = (size_t)(b * LL + k0 + r) * DD + h * DK + c4 * 4;
            float4 kv = *(const float4*)(K + goff);
            float4 vv = *(const float4*)(V + goff);
            float4 kc, vc;
            kc.x = __uint_as_float(f2tf(kv.x)); kc.y = __uint_as_float(f2tf(kv.y));
            kc.z = __uint_as_float(f2tf(kv.z)); kc.w = __uint_as_float(f2tf(kv.w));
            vc.x = __uint_as_float(f2tf(vv.x)); vc.y = __uint_as_float(f2tf(vv.y));
            vc.z = __uint_as_float(f2tf(vv.z)); vc.w = __uint_as_float(f2tf(vv.w));
            *(float4*)&Ks[r][c4 * 4] = kc;
            *(float4*)&Vs[r][c4 * 4] = vc;
        }
        __syncthreads();

        float s[8][4];
#pragma unroll
        for (int nt = 0; nt < 8; nt++)
#pragma unroll
            for (int r = 0; r < 4; r++) s[nt][r] = 0.0f;

#pragma unroll
        for (int ks = 0; ks < 8; ks++) {
            const int kk = ks * 8;
#pragma unroll
            for (int nt = 0; nt < 8; nt++) {
                uint32_t b0 = __float_as_uint(Ks[nt * 8 + g][kk + t]);
                uint32_t b1 = __float_as_uint(Ks[nt * 8 + g][kk + t + 4]);
                mma_tf32(s[nt][0], s[nt][1], s[nt][2], s[nt][3],
                         qa[ks][0], qa[ks][1], qa[ks][2], qa[ks][3], b0, b1);
            }
        }

        if (tt >= 2 * qt) {
#pragma unroll
            for (int nt = 0; nt < 8; nt++) {
                int col = k0 + nt * 8 + 2 * t;
                if (col     > rowA) s[nt][0] = -1e30f;
                if (col + 1 > rowA) s[nt][1] = -1e30f;
                if (col     > rowB) s[nt][2] = -1e30f;
                if (col + 1 > rowB) s[nt][3] = -1e30f;
            }
        }

        float mx0 = -1e30f, mx1 = -1e30f;
#pragma unroll
        for (int nt = 0; nt < 8; nt++) {
            mx0 = fmaxf(mx0, fmaxf(s[nt][0], s[nt][1]));
            mx1 = fmaxf(mx1, fmaxf(s[nt][2], s[nt][3]));
        }
        mx0 = fmaxf(mx0, __shfl_xor_sync(0xffffffffu, mx0, 1));
        mx0 = fmaxf(mx0, __shfl_xor_sync(0xffffffffu, mx0, 2));
        mx1 = fmaxf(mx1, __shfl_xor_sync(0xffffffffu, mx1, 1));
        mx1 = fmaxf(mx1, __shfl_xor_sync(0xffffffffu, mx1, 2));

        float mn0 = fmaxf(m0, mx0), mn1 = fmaxf(m1, mx1);
        float cr0 = __expf(m0 - mn0), cr1 = __expf(m1 - mn1);
        m0 = mn0; m1 = mn1;
        l0 *= cr0; l1 *= cr1;
#pragma unroll
        for (int nd = 0; nd < 8; nd++) {
            o[nd][0] *= cr0; o[nd][1] *= cr0;
            o[nd][2] *= cr1; o[nd][3] *= cr1;
        }

        float s0 = 0.0f, s1 = 0.0f;
#pragma unroll
        for (int nt = 0; nt < 8; nt++) {
            s[nt][0] = __expf(s[nt][0] - mn0);
            s[nt][1] = __expf(s[nt][1] - mn0);
            s[nt][2] = __expf(s[nt][2] - mn1);
            s[nt][3] = __expf(s[nt][3] - mn1);
            s0 += s[nt][0] + s[nt][1];
            s1 += s[nt][2] + s[nt][3];
        }
        s0 += __shfl_xor_sync(0xffffffffu, s0, 1);
        s0 += __shfl_xor_sync(0xffffffffu, s0, 2);
        s1 += __shfl_xor_sync(0xffffffffu, s1, 1);
        s1 += __shfl_xor_sync(0xffffffffu, s1, 2);
        l0 += s0; l1 += s1;

        const int src1 = (lane & 28) | (t >> 1);
#pragma unroll
        for (int ks = 0; ks < 8; ks++) {
            uint32_t u0 = f2tf(s[ks][0]), u1 = f2tf(s[ks][1]);
            uint32_t u2 = f2tf(s[ks][2]), u3 = f2tf(s[ks][3]);
            uint32_t x0 = __shfl_sync(0xffffffffu, u0, src1);
            uint32_t x1 = __shfl_sync(0xffffffffu, u1, src1);
            uint32_t x2 = __shfl_sync(0xffffffffu, u2, src1);
            uint32_t x3 = __shfl_sync(0xffffffffu, u3, src1);
            uint32_t y0 = __shfl_sync(0xffffffffu, u0, src1 + 2);
            uint32_t y1 = __shfl_sync(0xffffffffu, u1, src1 + 2);
            uint32_t y2 = __shfl_sync(0xffffffffu, u2, src1 + 2);
            uint32_t y3 = __shfl_sync(0xffffffffu, u3, src1 + 2);
            uint32_t a0 = (t & 1) ? x1 : x0;
            uint32_t a1 = (t & 1) ? x3 : x2;
            uint32_t a2 = (t & 1) ? y1 : y0;
            uint32_t a3 = (t & 1) ? y3 : y2;
#pragma unroll
            for (int nd = 0; nd < 8; nd++) {
                uint32_t b0 = __float_as_uint(Vs[ks * 8 + t][nd * 8 + g]);
                uint32_t b1 = __float_as_uint(Vs[ks * 8 + t + 4][nd * 8 + g]);
                mma_tf32(o[nd][0], o[nd][1], o[nd][2], o[nd][3],
                         a0, a1, a2, a3, b0, b1);
            }
        }
    }

    const float i0 = 1.0f / l0, i1 = 1.0f / l1;
#pragma unroll
    for (int nd = 0; nd < 8; nd++) {
        const int col = h * DK + nd * 8 + 2 * t;
        float2 vA = make_float2(o[nd][0] * i0, o[nd][1] * i0);
        float2 vB = make_float2(o[nd][2] * i1, o[nd][3] * i1);
        *(float2*)(ctx + (size_t)(b * LL + rowA) * DD + col) = vA;
        *(float2*)(ctx + (size_t)(b * LL + rowB) * DD + col) = vB;
    }
}

// ============================================================
// Launch
// ============================================================
extern "C" void kernel_launch(void* const* d_in, const int* in_sizes, int n_in,
                              void* d_out, int out_size) {
    const float* q    = (const float*)d_in[0];
    const float* k    = (const float*)d_in[1];
    const float* v    = (const float*)d_in[2];
    const float* wq_w = (const float*)d_in[3];
    const float* wq_b = (const float*)d_in[4];
    const float* wk_w = (const float*)d_in[5];
    const float* wk_b = (const float*)d_in[6];
    const float* wv_w = (const float*)d_in[7];
    const float* wv_b = (const float*)d_in[8];
    const float* wo_w = (const float*)d_in[9];
    const float* wo_b = (const float*)d_in[10];
    float* out = (float*)d_out;

    float *Qp, *Kp, *Vp, *Cp;
    cudaGetSymbolAddress((void**)&Qp, g_q);
    cudaGetSymbolAddress((void**)&Kp, g_k);
    cudaGetSymbolAddress((void**)&Vp, g_v);
    cudaGetSymbolAddress((void**)&Cp, g_ctx);

    const int M = BB * LL;  // 8192

    GemmArgs aq{q, wq_w, wq_b, Qp};
    GemmArgs ak{k, wk_w, wk_b, Kp};
    GemmArgs av{v, wv_w, wv_b, Vp};

    dim3 gq(DD / BN, M / BM, 3);  // (8, 64, 3) fused QKV
    gemm_qkv_kernel<<<gq, 256>>>(aq, ak, av, M, DD, DD);

    dim3 ga(LL / 128, HH, BB);  // (16, 16, 4)
    attn_mma_kernel<<<ga, 256>>>(Qp, Kp, Vp, Cp);

    dim3 gg(DD / BN, M / BM);  // (8, 64)
    gemm_tf32_kernel<<<gg, 256>>>(Cp, wo_w, wo_b, out, M, DD, DD);
}

// round 9
// speedup vs baseline: 3.7441x; 1.4023x over previous
#include <cuda_runtime.h>
#include <cstdint>

#define BB 4
#define LL 2048
#define DD 1024
#define HH 16
#define DK 64

// Scratch buffers (allocation-free rule: __device__ globals)
__device__ float g_q[BB * LL * DD];
__device__ float g_k[BB * LL * DD];
__device__ float g_v[BB * LL * DD];
__device__ float g_ctx[BB * LL * DD];

__device__ __forceinline__ uint32_t f2tf(float x) {
    uint32_t u;
    asm("cvt.rna.tf32.f32 %0, %1;" : "=r"(u) : "f"(x));
    return u;
}

__device__ __forceinline__ void mma_tf32(float& d0, float& d1, float& d2, float& d3,
                                         uint32_t a0, uint32_t a1, uint32_t a2, uint32_t a3,
                                         uint32_t b0, uint32_t b1) {
    asm volatile(
        "mma.sync.aligned.m16n8k8.row.col.f32.tf32.tf32.f32 "
        "{%0,%1,%2,%3}, {%4,%5,%6,%7}, {%8,%9}, {%0,%1,%2,%3};"
        : "+f"(d0), "+f"(d1), "+f"(d2), "+f"(d3)
        : "r"(a0), "r"(a1), "r"(a2), "r"(a3), "r"(b0), "r"(b1));
}

// ============================================================
// TF32 GEMM v2: C[M,N] = A[M,K] @ W[N,K]^T + bias[N]
// 4 warps (2x2), warp tile 64x64, CTA tile 128x128, BK=16.
// Permuted + swizzled smem: each thread's fragment data for a
// whole 16-k chunk is a single LDS.128.
//   store (row, c) at float idx: row*16 + (((c&3) ^ sw(row))<<2) + (c>>2)
//   sw(row) = (row ^ (row>>2)) & 3
//   thread (g,t) loads float4 at row*16 + ((t ^ sw(row))<<2)
//     -> cols {t, t+4, t+8, t+12} = a/b frags for ks0 (.x,.y) and ks1 (.z,.w)
// ============================================================
struct GemmArgs {
    const float* A;
    const float* W;
    const float* bias;
    float* C;
};

__device__ __forceinline__ int swz(int row) { return (row ^ (row >> 2)) & 3; }

__global__ __launch_bounds__(128, 2)
void gemm_v2_kernel(GemmArgs ga0, GemmArgs ga1, GemmArgs ga2,
                    int M, int N, int K) {
    __shared__ float Sa[2][128 * 16];
    __shared__ float Sb[2][128 * 16];

    GemmArgs ga = (blockIdx.z == 0) ? ga0 : (blockIdx.z == 1) ? ga1 : ga2;

    const int tid  = threadIdx.x;
    const int warp = tid >> 5;
    const int lane = tid & 31;
    const int wm = warp >> 1;         // 0..1
    const int wn = warp & 1;          // 0..1
    const int g  = lane >> 2;         // 0..7
    const int t  = lane & 3;          // 0..3
    const int m0 = wm * 64;
    const int n0 = wn * 64;

    const int bm = blockIdx.y;
    const int bn = blockIdx.x;

    const float* Ab = ga.A + (size_t)(bm * 128) * K;
    const float* Wb = ga.W + (size_t)(bn * 128) * K;

    // global load mapping: 512 float4 per tensor per stage, 4 per thread
    const int lr = tid >> 2;          // row base (+32*i)
    const int lc = tid & 3;           // float4 col within 16 floats

    float acc[4][8][4];
#pragma unroll
    for (int i = 0; i < 4; i++)
#pragma unroll
        for (int j = 0; j < 8; j++)
#pragma unroll
            for (int r = 0; r < 4; r++) acc[i][j][r] = 0.0f;

    float4 pa[4], pb[4];

#define LDG_STEP(s_)                                                              \
    do {                                                                          \
        const size_t ko = (size_t)(s_) * 16 + lc * 4;                             \
        _Pragma("unroll")                                                         \
        for (int i = 0; i < 4; i++) {                                             \
            const int row = lr + i * 32;                                          \
            pa[i] = *(const float4*)(Ab + (size_t)row * K + ko);                  \
            pb[i] = *(const float4*)(Wb + (size_t)row * K + ko);                  \
        }                                                                         \
    } while (0)

#define STS_STEP(st_)                                                             \
    do {                                                                          \
        _Pragma("unroll")                                                         \
        for (int i = 0; i < 4; i++) {                                             \
            const int row = lr + i * 32;                                          \
            const int sw = swz(row);                                              \
            float* da = &Sa[st_][row * 16 + lc];                                  \
            float* db = &Sb[st_][row * 16 + lc];                                  \
            da[((0 ^ sw) << 2)] = __uint_as_float(f2tf(pa[i].x));                 \
            da[((1 ^ sw) << 2)] = __uint_as_float(f2tf(pa[i].y));                 \
            da[((2 ^ sw) << 2)] = __uint_as_float(f2tf(pa[i].z));                 \
            da[((3 ^ sw) << 2)] = __uint_as_float(f2tf(pa[i].w));                 \
            db[((0 ^ sw) << 2)] = __uint_as_float(f2tf(pb[i].x));                 \
            db[((1 ^ sw) << 2)] = __uint_as_float(f2tf(pb[i].y));                 \
            db[((2 ^ sw) << 2)] = __uint_as_float(f2tf(pb[i].z));                 \
            db[((3 ^ sw) << 2)] = __uint_as_float(f2tf(pb[i].w));                 \
        }                                                                         \
    } while (0)

    const int NIT = K / 16;   // 64

    LDG_STEP(0);
    STS_STEP(0);
    __syncthreads();

    for (int s = 0; s < NIT; s++) {
        const int cur = s & 1;
        if (s + 1 < NIT) LDG_STEP(s + 1);

        // fragment loads: one LDS.128 per row
        float4 alo[4], ahi[4], bf[8];
#pragma unroll
        for (int mt = 0; mt < 4; mt++) {
            const int rlo = m0 + mt * 16 + g;
            alo[mt] = *(const float4*)&Sa[cur][rlo * 16 + ((t ^ swz(rlo)) << 2)];
            const int rhi = rlo + 8;
            ahi[mt] = *(const float4*)&Sa[cur][rhi * 16 + ((t ^ swz(rhi)) << 2)];
        }
#pragma unroll
        for (int nt = 0; nt < 8; nt++) {
            const int rb = n0 + nt * 8 + g;
            bf[nt] = *(const float4*)&Sb[cur][rb * 16 + ((t ^ swz(rb)) << 2)];
        }

        // ks0: cols (t, t+4)
#pragma unroll
        for (int mt = 0; mt < 4; mt++)
#pragma unroll
            for (int nt = 0; nt < 8; nt++)
                mma_tf32(acc[mt][nt][0], acc[mt][nt][1], acc[mt][nt][2], acc[mt][nt][3],
                         __float_as_uint(alo[mt].x), __float_as_uint(ahi[mt].x),
                         __float_as_uint(alo[mt].y), __float_as_uint(ahi[mt].y),
                         __float_as_uint(bf[nt].x),  __float_as_uint(bf[nt].y));
        // ks1: cols (t+8, t+12)
#pragma unroll
        for (int mt = 0; mt < 4; mt++)
#pragma unroll
            for (int nt = 0; nt < 8; nt++)
                mma_tf32(acc[mt][nt][0], acc[mt][nt][1], acc[mt][nt][2], acc[mt][nt][3],
                         __float_as_uint(alo[mt].z), __float_as_uint(ahi[mt].z),
                         __float_as_uint(alo[mt].w), __float_as_uint(ahi[mt].w),
                         __float_as_uint(bf[nt].z),  __float_as_uint(bf[nt].w));

        if (s + 1 < NIT) STS_STEP((s + 1) & 1);
        __syncthreads();
    }

#undef LDG_STEP
#undef STS_STEP

    // epilogue: bias + float2 stores (c-frag native layout)
#pragma unroll
    for (int mt = 0; mt < 4; mt++) {
        const int row0 = bm * 128 + m0 + mt * 16 + g;
#pragma unroll
        for (int nt = 0; nt < 8; nt++) {
            const int col = bn * 128 + n0 + nt * 8 + 2 * t;
            const float b0 = ga.bias[col];
            const float b1 = ga.bias[col + 1];
            float2 v0 = make_float2(acc[mt][nt][0] + b0, acc[mt][nt][1] + b1);
            float2 v1 = make_float2(acc[mt][nt][2] + b0, acc[mt][nt][3] + b1);
            *(float2*)(ga.C + (size_t)row0 * N + col)       = v0;
            *(float2*)(ga.C + (size_t)(row0 + 8) * N + col) = v1;
        }
    }
}

// ============================================================
// Tensor-core causal flash attention (tf32 legacy mma). Unchanged.
// ============================================================
#define KSTR 68
#define VSTR 72

__global__ __launch_bounds__(256, 2)
void attn_mma_kernel(const float* __restrict__ Q,
                     const float* __restrict__ K,
                     const float* __restrict__ V,
                     float* __restrict__ ctx) {
    __shared__ float Ks[64][KSTR];
    __shared__ float Vs[64][VSTR];

    const int tid  = threadIdx.x;
    const int warp = tid >> 5;
    const int lane = tid & 31;
    const int g = lane >> 2;
    const int t = lane & 3;

    const int qt = (int)gridDim.x - 1 - (int)blockIdx.x;
    const int h  = blockIdx.y;
    const int b  = blockIdx.z;

    const int q0   = qt * 128;
    const int rowA = q0 + warp * 16 + g;
    const int rowB = rowA + 8;

    uint32_t qa[8][4];
    {
        const float* qA = Q + (size_t)(b * LL + rowA) * DD + h * DK;
        const float* qB = Q + (size_t)(b * LL + rowB) * DD + h * DK;
#pragma unroll
        for (int ks = 0; ks < 8; ks++) {
            qa[ks][0] = f2tf(qA[ks * 8 + t] * 0.125f);
            qa[ks][1] = f2tf(qB[ks * 8 + t] * 0.125f);
            qa[ks][2] = f2tf(qA[ks * 8 + t + 4] * 0.125f);
            qa[ks][3] = f2tf(qB[ks * 8 + t + 4] * 0.125f);
        }
    }

    float o[8][4];
#pragma unroll
    for (int nd = 0; nd < 8; nd++)
#pragma unroll
        for (int r = 0; r < 4; r++) o[nd][r] = 0.0f;
    float m0 = -1e30f, m1 = -1e30f, l0 = 0.0f, l1 = 0.0f;

    const int ntiles = 2 * qt + 2;

    for (int tt = 0; tt < ntiles; tt++) {
        const int k0 = tt * 64;
        __syncthreads();
        for (int i = tid; i < 64 * 16; i += 256) {
            int r  = i >> 4;
            int c4 = i & 15;
            size_t goff = (size_t)(b * LL + k0 + r) * DD + h * DK + c4 * 4;
            float4 kv = *(const float4*)(K + goff);
            float4 vv = *(const float4*)(V + goff);
            float4 kc, vc;
            kc.x = __uint_as_float(f2tf(kv.x)); kc.y = __uint_as_float(f2tf(kv.y));
            kc.z = __uint_as_float(f2tf(kv.z)); kc.w = __uint_as_float(f2tf(kv.w));
            vc.x = __uint_as_float(f2tf(vv.x)); vc.y = __uint_as_float(f2tf(vv.y));
            vc.z = __uint_as_float(f2tf(vv.z)); vc.w = __uint_as_float(f2tf(vv.w));
            *(float4*)&Ks[r][c4 * 4] = kc;
            *(float4*)&Vs[r][c4 * 4] = vc;
        }
        __syncthreads();

        float s[8][4];
#pragma unroll
        for (int nt = 0; nt < 8; nt++)
#pragma unroll
            for (int r = 0; r < 4; r++) s[nt][r] = 0.0f;

#pragma unroll
        for (int ks = 0; ks < 8; ks++) {
            const int kk = ks * 8;
#pragma unroll
            for (int nt = 0; nt < 8; nt++) {
                uint32_t b0 = __float_as_uint(Ks[nt * 8 + g][kk + t]);
                uint32_t b1 = __float_as_uint(Ks[nt * 8 + g][kk + t + 4]);
                mma_tf32(s[nt][0], s[nt][1], s[nt][2], s[nt][3],
                         qa[ks][0], qa[ks][1], qa[ks][2], qa[ks][3], b0, b1);
            }
        }

        if (tt >= 2 * qt) {
#pragma unroll
            for (int nt = 0; nt < 8; nt++) {
                int col = k0 + nt * 8 + 2 * t;
                if (col     > rowA) s[nt][0] = -1e30f;
                if (col + 1 > rowA) s[nt][1] = -1e30f;
                if (col     > rowB) s[nt][2] = -1e30f;
                if (col + 1 > rowB) s[nt][3] = -1e30f;
            }
        }

        float mx0 = -1e30f, mx1 = -1e30f;
#pragma unroll
        for (int nt = 0; nt < 8; nt++) {
            mx0 = fmaxf(mx0, fmaxf(s[nt][0], s[nt][1]));
            mx1 = fmaxf(mx1, fmaxf(s[nt][2], s[nt][3]));
        }
        mx0 = fmaxf(mx0, __shfl_xor_sync(0xffffffffu, mx0, 1));
        mx0 = fmaxf(mx0, __shfl_xor_sync(0xffffffffu, mx0, 2));
        mx1 = fmaxf(mx1, __shfl_xor_sync(0xffffffffu, mx1, 1));
        mx1 = fmaxf(mx1, __shfl_xor_sync(0xffffffffu, mx1, 2));

        float mn0 = fmaxf(m0, mx0), mn1 = fmaxf(m1, mx1);
        float cr0 = __expf(m0 - mn0), cr1 = __expf(m1 - mn1);
        m0 = mn0; m1 = mn1;
        l0 *= cr0; l1 *= cr1;
#pragma unroll
        for (int nd = 0; nd < 8; nd++) {
            o[nd][0] *= cr0; o[nd][1] *= cr0;
            o[nd][2] *= cr1; o[nd][3] *= cr1;
        }

        float s0 = 0.0f, s1 = 0.0f;
#pragma unroll
        for (int nt = 0; nt < 8; nt++) {
            s[nt][0] = __expf(s[nt][0] - mn0);
            s[nt][1] = __expf(s[nt][1] - mn0);
            s[nt][2] = __expf(s[nt][2] - mn1);
            s[nt][3] = __expf(s[nt][3] - mn1);
            s0 += s[nt][0] + s[nt][1];
            s1 += s[nt][2] + s[nt][3];
        }
        s0 += __shfl_xor_sync(0xffffffffu, s0, 1);
        s0 += __shfl_xor_sync(0xffffffffu, s0, 2);
        s1 += __shfl_xor_sync(0xffffffffu, s1, 1);
        s1 += __shfl_xor_sync(0xffffffffu, s1, 2);
        l0 += s0; l1 += s1;

        const int src1 = (lane & 28) | (t >> 1);
#pragma unroll
        for (int ks = 0; ks < 8; ks++) {
            uint32_t u0 = f2tf(s[ks][0]), u1 = f2tf(s[ks][1]);
            uint32_t u2 = f2tf(s[ks][2]), u3 = f2tf(s[ks][3]);
            uint32_t x0 = __shfl_sync(0xffffffffu, u0, src1);
            uint32_t x1 = __shfl_sync(0xffffffffu, u1, src1);
            uint32_t x2 = __shfl_sync(0xffffffffu, u2, src1);
            uint32_t x3 = __shfl_sync(0xffffffffu, u3, src1);
            uint32_t y0 = __shfl_sync(0xffffffffu, u0, src1 + 2);
            uint32_t y1 = __shfl_sync(0xffffffffu, u1, src1 + 2);
            uint32_t y2 = __shfl_sync(0xffffffffu, u2, src1 + 2);
            uint32_t y3 = __shfl_sync(0xffffffffu, u3, src1 + 2);
            uint32_t a0 = (t & 1) ? x1 : x0;
            uint32_t a1 = (t & 1) ? x3 : x2;
            uint32_t a2 = (t & 1) ? y1 : y0;
            uint32_t a3 = (t & 1) ? y3 : y2;
#pragma unroll
            for (int nd = 0; nd < 8; nd++) {
                uint32_t b0 = __float_as_uint(Vs[ks * 8 + t][nd * 8 + g]);
                uint32_t b1 = __float_as_uint(Vs[ks * 8 + t + 4][nd * 8 + g]);
                mma_tf32(o[nd][0], o[nd][1], o[nd][2], o[nd][3],
                         a0, a1, a2, a3, b0, b1);
            }
        }
    }

    const float i0 = 1.0f / l0, i1 = 1.0f / l1;
#pragma unroll
    for (int nd = 0; nd < 8; nd++) {
        const int col = h * DK + nd * 8 + 2 * t;
        float2 vA = make_float2(o[nd][0] * i0, o[nd][1] * i0);
        float2 vB = make_float2(o[nd][2] * i1, o[nd][3] * i1);
        *(float2*)(ctx + (size_t)(b * LL + rowA) * DD + col) = vA;
        *(float2*)(ctx + (size_t)(b * LL + rowB) * DD + col) = vB;
    }
}

// ============================================================
// Launch
// ============================================================
extern "C" void kernel_launch(void* const* d_in, const int* in_sizes, int n_in,
                              void* d_out, int out_size) {
    const float* q    = (const float*)d_in[0];
    const float* k    = (const float*)d_in[1];
    const float* v    = (const float*)d_in[2];
    const float* wq_w = (const float*)d_in[3];
    const float* wq_b = (const float*)d_in[4];
    const float* wk_w = (const float*)d_in[5];
    const float* wk_b = (const float*)d_in[6];
    const float* wv_w = (const float*)d_in[7];
    const float* wv_b = (const float*)d_in[8];
    const float* wo_w = (const float*)d_in[9];
    const float* wo_b = (const float*)d_in[10];
    float* out = (float*)d_out;

    float *Qp, *Kp, *Vp, *Cp;
    cudaGetSymbolAddress((void**)&Qp, g_q);
    cudaGetSymbolAddress((void**)&Kp, g_k);
    cudaGetSymbolAddress((void**)&Vp, g_v);
    cudaGetSymbolAddress((void**)&Cp, g_ctx);

    const int M = BB * LL;  // 8192

    GemmArgs aq{q, wq_w, wq_b, Qp};
    GemmArgs ak{k, wk_w, wk_b, Kp};
    GemmArgs av{v, wv_w, wv_b, Vp};
    GemmArgs ao{Cp, wo_w, wo_b, out};

    dim3 gq(DD / 128, M / 128, 3);  // (8, 64, 3) fused QKV
    gemm_v2_kernel<<<gq, 128>>>(aq, ak, av, M, DD, DD);

    dim3 ga(LL / 128, HH, BB);  // (16, 16, 4)
    attn_mma_kernel<<<ga, 256>>>(Qp, Kp, Vp, Cp);

    dim3 go(DD / 128, M / 128, 1);  // (8, 64)
    gemm_v2_kernel<<<go, 128>>>(ao, ao, ao, M, DD, DD);
}

// round 12
// speedup vs baseline: 3.7985x; 1.0145x over previous
#include <cuda_runtime.h>
#include <cstdint>

#define BB 4
#define LL 2048
#define DD 1024
#define HH 16
#define DK 64

// Scratch buffers (allocation-free rule: __device__ globals)
__device__ float g_q[BB * LL * DD];
__device__ float g_k[BB * LL * DD];
__device__ float g_v[BB * LL * DD];
__device__ float g_ctx[BB * LL * DD];

__device__ __forceinline__ uint32_t f2tf(float x) {
    uint32_t u;
    asm("cvt.rna.tf32.f32 %0, %1;" : "=r"(u) : "f"(x));
    return u;
}

__device__ __forceinline__ void mma_tf32(float& d0, float& d1, float& d2, float& d3,
                                         uint32_t a0, uint32_t a1, uint32_t a2, uint32_t a3,
                                         uint32_t b0, uint32_t b1) {
    asm volatile(
        "mma.sync.aligned.m16n8k8.row.col.f32.tf32.tf32.f32 "
        "{%0,%1,%2,%3}, {%4,%5,%6,%7}, {%8,%9}, {%0,%1,%2,%3};"
        : "+f"(d0), "+f"(d1), "+f"(d2), "+f"(d3)
        : "r"(a0), "r"(a1), "r"(a2), "r"(a3), "r"(b0), "r"(b1));
}

// ============================================================
// TF32 GEMM v2 (unchanged structure from R8; adds optional
// tf32 rounding of outputs so attention can skip cvt).
// ============================================================
struct GemmArgs {
    const float* A;
    const float* W;
    const float* bias;
    float* C;
    int round_out;   // 1: round outputs to tf32 (QKV), 0: plain fp32 (WO)
};

__device__ __forceinline__ int swz(int row) { return (row ^ (row >> 2)) & 3; }

__global__ __launch_bounds__(128, 2)
void gemm_v2_kernel(GemmArgs ga0, GemmArgs ga1, GemmArgs ga2,
                    int M, int N, int K) {
    __shared__ float Sa[2][128 * 16];
    __shared__ float Sb[2][128 * 16];

    GemmArgs ga = (blockIdx.z == 0) ? ga0 : (blockIdx.z == 1) ? ga1 : ga2;

    const int tid  = threadIdx.x;
    const int warp = tid >> 5;
    const int lane = tid & 31;
    const int wm = warp >> 1;
    const int wn = warp & 1;
    const int g  = lane >> 2;
    const int t  = lane & 3;
    const int m0 = wm * 64;
    const int n0 = wn * 64;

    const int bm = blockIdx.y;
    const int bn = blockIdx.x;

    const float* Ab = ga.A + (size_t)(bm * 128) * K;
    const float* Wb = ga.W + (size_t)(bn * 128) * K;

    const int lr = tid >> 2;
    const int lc = tid & 3;

    float acc[4][8][4];
#pragma unroll
    for (int i = 0; i < 4; i++)
#pragma unroll
        for (int j = 0; j < 8; j++)
#pragma unroll
            for (int r = 0; r < 4; r++) acc[i][j][r] = 0.0f;

    float4 pa[4], pb[4];

#define LDG_STEP(s_)                                                              \
    do {                                                                          \
        const size_t ko = (size_t)(s_) * 16 + lc * 4;                             \
        _Pragma("unroll")                                                         \
        for (int i = 0; i < 4; i++) {                                             \
            const int row = lr + i * 32;                                          \
            pa[i] = *(const float4*)(Ab + (size_t)row * K + ko);                  \
            pb[i] = *(const float4*)(Wb + (size_t)row * K + ko);                  \
        }                                                                         \
    } while (0)

#define STS_STEP(st_)                                                             \
    do {                                                                          \
        _Pragma("unroll")                                                         \
        for (int i = 0; i < 4; i++) {                                             \
            const int row = lr + i * 32;                                          \
            const int sw = swz(row);                                              \
            float* da = &Sa[st_][row * 16 + lc];                                  \
            float* db = &Sb[st_][row * 16 + lc];                                  \
            da[((0 ^ sw) << 2)] = __uint_as_float(f2tf(pa[i].x));                 \
            da[((1 ^ sw) << 2)] = __uint_as_float(f2tf(pa[i].y));                 \
            da[((2 ^ sw) << 2)] = __uint_as_float(f2tf(pa[i].z));                 \
            da[((3 ^ sw) << 2)] = __uint_as_float(f2tf(pa[i].w));                 \
            db[((0 ^ sw) << 2)] = __uint_as_float(f2tf(pb[i].x));                 \
            db[((1 ^ sw) << 2)] = __uint_as_float(f2tf(pb[i].y));                 \
            db[((2 ^ sw) << 2)] = __uint_as_float(f2tf(pb[i].z));                 \
            db[((3 ^ sw) << 2)] = __uint_as_float(f2tf(pb[i].w));                 \
        }                                                                         \
    } while (0)

    const int NIT = K / 16;

    LDG_STEP(0);
    STS_STEP(0);
    __syncthreads();

    for (int s = 0; s < NIT; s++) {
        const int cur = s & 1;
        if (s + 1 < NIT) LDG_STEP(s + 1);

        float4 alo[4], ahi[4], bf[8];
#pragma unroll
        for (int mt = 0; mt < 4; mt++) {
            const int rlo = m0 + mt * 16 + g;
            alo[mt] = *(const float4*)&Sa[cur][rlo * 16 + ((t ^ swz(rlo)) << 2)];
            const int rhi = rlo + 8;
            ahi[mt] = *(const float4*)&Sa[cur][rhi * 16 + ((t ^ swz(rhi)) << 2)];
        }
#pragma unroll
        for (int nt = 0; nt < 8; nt++) {
            const int rb = n0 + nt * 8 + g;
            bf[nt] = *(const float4*)&Sb[cur][rb * 16 + ((t ^ swz(rb)) << 2)];
        }

#pragma unroll
        for (int mt = 0; mt < 4; mt++)
#pragma unroll
            for (int nt = 0; nt < 8; nt++)
                mma_tf32(acc[mt][nt][0], acc[mt][nt][1], acc[mt][nt][2], acc[mt][nt][3],
                         __float_as_uint(alo[mt].x), __float_as_uint(ahi[mt].x),
                         __float_as_uint(alo[mt].y), __float_as_uint(ahi[mt].y),
                         __float_as_uint(bf[nt].x),  __float_as_uint(bf[nt].y));
#pragma unroll
        for (int mt = 0; mt < 4; mt++)
#pragma unroll
            for (int nt = 0; nt < 8; nt++)
                mma_tf32(acc[mt][nt][0], acc[mt][nt][1], acc[mt][nt][2], acc[mt][nt][3],
                         __float_as_uint(alo[mt].z), __float_as_uint(ahi[mt].z),
                         __float_as_uint(alo[mt].w), __float_as_uint(ahi[mt].w),
                         __float_as_uint(bf[nt].z),  __float_as_uint(bf[nt].w));

        if (s + 1 < NIT) STS_STEP((s + 1) & 1);
        __syncthreads();
    }

#undef LDG_STEP
#undef STS_STEP

#pragma unroll
    for (int mt = 0; mt < 4; mt++) {
        const int row0 = bm * 128 + m0 + mt * 16 + g;
#pragma unroll
        for (int nt = 0; nt < 8; nt++) {
            const int col = bn * 128 + n0 + nt * 8 + 2 * t;
            const float b0 = ga.bias[col];
            const float b1 = ga.bias[col + 1];
            float2 v0 = make_float2(acc[mt][nt][0] + b0, acc[mt][nt][1] + b1);
            float2 v1 = make_float2(acc[mt][nt][2] + b0, acc[mt][nt][3] + b1);
            if (ga.round_out) {
                v0.x = __uint_as_float(f2tf(v0.x)); v0.y = __uint_as_float(f2tf(v0.y));
                v1.x = __uint_as_float(f2tf(v1.x)); v1.y = __uint_as_float(f2tf(v1.y));
            }
            *(float2*)(ga.C + (size_t)row0 * N + col)       = v0;
            *(float2*)(ga.C + (size_t)(row0 + 8) * N + col) = v1;
        }
    }
}

// ============================================================
// Attention v2: 4 warps x 32 q-rows (2 m-tiles/warp), 64-key tiles.
// K in smem permuted for LDS.128 fragment loads; V transposed+permuted.
// Inputs Q/K/V are tf32-exact (pre-rounded by QKV GEMM) -> no cvt here.
//   layout: row r of 64 floats = 4 chunks of 16; chunk ch stored at
//   slot ((ch+r)&3)*16; element c of chunk at ((c&3)^sw(r))<<2 | (c>>2),
//   sw(r)=(r^(r>>2))&3. Fragment (g,t): LDS.128 at slot + ((t^sw)<<2)
//   -> elements {t, t+4, t+8, t+12} of the chunk. Conflict-free.
// ============================================================
__global__ __launch_bounds__(128, 2)
void attn_v2_kernel(const float* __restrict__ Q,
                    const float* __restrict__ K,
                    const float* __restrict__ V,
                    float* __restrict__ ctx) {
    __shared__ float Ks[64 * 64];
    __shared__ float Vt[64 * 64];

    const int tid  = threadIdx.x;
    const int warp = tid >> 5;
    const int lane = tid & 31;
    const int g = lane >> 2;
    const int t = lane & 3;

    const int qt = (int)gridDim.x - 1 - (int)blockIdx.x;  // heavy tiles first
    const int h  = blockIdx.y;
    const int b  = blockIdx.z;

    const int q0 = qt * 128;
    // rows per m-tile
    int rA[2], rB[2];
#pragma unroll
    for (int mt = 0; mt < 2; mt++) {
        rA[mt] = q0 + warp * 32 + mt * 16 + g;
        rB[mt] = rA[mt] + 8;
    }

    // Q fragments (gmem values are tf32-exact; *0.125f is exact)
    uint32_t qa[2][8][4];
#pragma unroll
    for (int mt = 0; mt < 2; mt++) {
        const float* qAp = Q + (size_t)(b * LL + rA[mt]) * DD + h * DK;
        const float* qBp = Q + (size_t)(b * LL + rB[mt]) * DD + h * DK;
#pragma unroll
        for (int ks = 0; ks < 8; ks++) {
            qa[mt][ks][0] = __float_as_uint(qAp[ks * 8 + t] * 0.125f);
            qa[mt][ks][1] = __float_as_uint(qBp[ks * 8 + t] * 0.125f);
            qa[mt][ks][2] = __float_as_uint(qAp[ks * 8 + t + 4] * 0.125f);
            qa[mt][ks][3] = __float_as_uint(qBp[ks * 8 + t + 4] * 0.125f);
        }
    }

    float o[2][8][4];
#pragma unroll
    for (int mt = 0; mt < 2; mt++)
#pragma unroll
        for (int nd = 0; nd < 8; nd++)
#pragma unroll
            for (int r = 0; r < 4; r++) o[mt][nd][r] = 0.0f;
    float mA[2] = {-1e30f, -1e30f}, mB[2] = {-1e30f, -1e30f};
    float lA[2] = {0.0f, 0.0f},    lB[2] = {0.0f, 0.0f};

    const int ntiles = 2 * qt + 2;

    for (int tt = 0; tt < ntiles; tt++) {
        const int k0 = tt * 64;
        __syncthreads();
        // cooperative K/V tile load with permuted stores (8 float4/thread/tensor)
#pragma unroll
        for (int j = 0; j < 8; j++) {
            const int i = tid + j * 128;
            const int r  = i >> 4;    // key row 0..63
            const int c4 = i & 15;    // float4 along dk
            const size_t goff = (size_t)(b * LL + k0 + r) * DD + h * DK + c4 * 4;
            float4 kv = *(const float4*)(K + goff);
            float4 vv = *(const float4*)(V + goff);
            // K: row=r (key), chunk ch=c4>>2 over dk, elems c=(c4&3)*4+e
            {
                const int sw = swz(r);
                float* kd = &Ks[r * 64 + (((c4 >> 2) + r) & 3) * 16 + (c4 & 3)];
                kd[((0 ^ sw) << 2)] = kv.x;
                kd[((1 ^ sw) << 2)] = kv.y;
                kd[((2 ^ sw) << 2)] = kv.z;
                kd[((3 ^ sw) << 2)] = kv.w;
            }
            // V transposed: rows = dk (c4*4+e), key chunk kch=r>>4, elem kc=r&15
            {
                const int kch = r >> 4;
                const int kc  = r & 15;
                float vals[4] = {vv.x, vv.y, vv.z, vv.w};
#pragma unroll
                for (int e = 0; e < 4; e++) {
                    const int rd = c4 * 4 + e;
                    const int swd = swz(rd);
                    Vt[rd * 64 + ((kch + rd) & 3) * 16 +
                       (((kc & 3) ^ swd) << 2) + (kc >> 2)] = vals[e];
                }
            }
        }
        __syncthreads();

        // ---------- S = Q K^T ----------
        float s[2][8][4];
#pragma unroll
        for (int mt = 0; mt < 2; mt++)
#pragma unroll
            for (int nt = 0; nt < 8; nt++)
#pragma unroll
                for (int r = 0; r < 4; r++) s[mt][nt][r] = 0.0f;

#pragma unroll
        for (int ch = 0; ch < 4; ch++) {
            float4 bf[8];
#pragma unroll
            for (int nt = 0; nt < 8; nt++) {
                const int rk = nt * 8 + g;
                bf[nt] = *(const float4*)&Ks[rk * 64 + ((ch + rk) & 3) * 16 +
                                             ((t ^ swz(rk)) << 2)];
            }
#pragma unroll
            for (int mt = 0; mt < 2; mt++)
#pragma unroll
                for (int nt = 0; nt < 8; nt++) {
                    mma_tf32(s[mt][nt][0], s[mt][nt][1], s[mt][nt][2], s[mt][nt][3],
                             qa[mt][2 * ch][0], qa[mt][2 * ch][1],
                             qa[mt][2 * ch][2], qa[mt][2 * ch][3],
                             __float_as_uint(bf[nt].x), __float_as_uint(bf[nt].y));
                    mma_tf32(s[mt][nt][0], s[mt][nt][1], s[mt][nt][2], s[mt][nt][3],
                             qa[mt][2 * ch + 1][0], qa[mt][2 * ch + 1][1],
                             qa[mt][2 * ch + 1][2], qa[mt][2 * ch + 1][3],
                             __float_as_uint(bf[nt].z), __float_as_uint(bf[nt].w));
                }
        }

        // causal mask on the two diagonal tiles
        if (tt >= 2 * qt) {
#pragma unroll
            for (int mt = 0; mt < 2; mt++)
#pragma unroll
                for (int nt = 0; nt < 8; nt++) {
                    int col = k0 + nt * 8 + 2 * t;
                    if (col     > rA[mt]) s[mt][nt][0] = -1e30f;
                    if (col + 1 > rA[mt]) s[mt][nt][1] = -1e30f;
                    if (col     > rB[mt]) s[mt][nt][2] = -1e30f;
                    if (col + 1 > rB[mt]) s[mt][nt][3] = -1e30f;
                }
        }

        // ---------- online softmax (per m-tile) ----------
#pragma unroll
        for (int mt = 0; mt < 2; mt++) {
            float mx0 = -1e30f, mx1 = -1e30f;
#pragma unroll
            for (int nt = 0; nt < 8; nt++) {
                mx0 = fmaxf(mx0, fmaxf(s[mt][nt][0], s[mt][nt][1]));
                mx1 = fmaxf(mx1, fmaxf(s[mt][nt][2], s[mt][nt][3]));
            }
            mx0 = fmaxf(mx0, __shfl_xor_sync(0xffffffffu, mx0, 1));
            mx0 = fmaxf(mx0, __shfl_xor_sync(0xffffffffu, mx0, 2));
            mx1 = fmaxf(mx1, __shfl_xor_sync(0xffffffffu, mx1, 1));
            mx1 = fmaxf(mx1, __shfl_xor_sync(0xffffffffu, mx1, 2));

            float mn0 = fmaxf(mA[mt], mx0), mn1 = fmaxf(mB[mt], mx1);
            float cr0 = __expf(mA[mt] - mn0), cr1 = __expf(mB[mt] - mn1);
            mA[mt] = mn0; mB[mt] = mn1;
            lA[mt] *= cr0; lB[mt] *= cr1;
#pragma unroll
            for (int nd = 0; nd < 8; nd++) {
                o[mt][nd][0] *= cr0; o[mt][nd][1] *= cr0;
                o[mt][nd][2] *= cr1; o[mt][nd][3] *= cr1;
            }

            float s0 = 0.0f, s1 = 0.0f;
#pragma unroll
            for (int nt = 0; nt < 8; nt++) {
                s[mt][nt][0] = __expf(s[mt][nt][0] - mn0);
                s[mt][nt][1] = __expf(s[mt][nt][1] - mn0);
                s[mt][nt][2] = __expf(s[mt][nt][2] - mn1);
                s[mt][nt][3] = __expf(s[mt][nt][3] - mn1);
                s0 += s[mt][nt][0] + s[mt][nt][1];
                s1 += s[mt][nt][2] + s[mt][nt][3];
            }
            s0 += __shfl_xor_sync(0xffffffffu, s0, 1);
            s0 += __shfl_xor_sync(0xffffffffu, s0, 2);
            s1 += __shfl_xor_sync(0xffffffffu, s1, 1);
            s1 += __shfl_xor_sync(0xffffffffu, s1, 2);
            lA[mt] += s0; lB[mt] += s1;
        }

        // ---------- O += P V ----------
        const int src1 = (lane & 28) | (t >> 1);
#pragma unroll
        for (int ch = 0; ch < 4; ch++) {
            float4 bf[8];
#pragma unroll
            for (int nd = 0; nd < 8; nd++) {
                const int rd = nd * 8 + g;
                bf[nd] = *(const float4*)&Vt[rd * 64 + ((ch + rd) & 3) * 16 +
                                             ((t ^ swz(rd)) << 2)];
            }
#pragma unroll
            for (int mt = 0; mt < 2; mt++)
#pragma unroll
                for (int kh = 0; kh < 2; kh++) {
                    const int ks = 2 * ch + kh;
                    uint32_t u0 = f2tf(s[mt][ks][0]), u1 = f2tf(s[mt][ks][1]);
                    uint32_t u2 = f2tf(s[mt][ks][2]), u3 = f2tf(s[mt][ks][3]);
                    uint32_t x0 = __shfl_sync(0xffffffffu, u0, src1);
                    uint32_t x1 = __shfl_sync(0xffffffffu, u1, src1);
                    uint32_t x2 = __shfl_sync(0xffffffffu, u2, src1);
                    uint32_t x3 = __shfl_sync(0xffffffffu, u3, src1);
                    uint32_t y0 = __shfl_sync(0xffffffffu, u0, src1 + 2);
                    uint32_t y1 = __shfl_sync(0xffffffffu, u1, src1 + 2);
                    uint32_t y2 = __shfl_sync(0xffffffffu, u2, src1 + 2);
                    uint32_t y3 = __shfl_sync(0xffffffffu, u3, src1 + 2);
                    uint32_t a0 = (t & 1) ? x1 : x0;
                    uint32_t a1 = (t & 1) ? x3 : x2;
                    uint32_t a2 = (t & 1) ? y1 : y0;
                    uint32_t a3 = (t & 1) ? y3 : y2;
#pragma unroll
                    for (int nd = 0; nd < 8; nd++) {
                        uint32_t b0 = kh ? __float_as_uint(bf[nd].z)
                                         : __float_as_uint(bf[nd].x);
                        uint32_t b1 = kh ? __float_as_uint(bf[nd].w)
                                         : __float_as_uint(bf[nd].y);
                        mma_tf32(o[mt][nd][0], o[mt][nd][1], o[mt][nd][2], o[mt][nd][3],
                                 a0, a1, a2, a3, b0, b1);
                    }
                }
        }
    }

    // ---------- epilogue ----------
#pragma unroll
    for (int mt = 0; mt < 2; mt++) {
        const float i0 = 1.0f / lA[mt], i1 = 1.0f / lB[mt];
#pragma unroll
        for (int nd = 0; nd < 8; nd++) {
            const int col = h * DK + nd * 8 + 2 * t;
            float2 vA = make_float2(o[mt][nd][0] * i0, o[mt][nd][1] * i0);
            float2 vB = make_float2(o[mt][nd][2] * i1, o[mt][nd][3] * i1);
            *(float2*)(ctx + (size_t)(b * LL + rA[mt]) * DD + col) = vA;
            *(float2*)(ctx + (size_t)(b * LL + rB[mt]) * DD + col) = vB;
        }
    }
}

// ============================================================
// Launch
// ============================================================
extern "C" void kernel_launch(void* const* d_in, const int* in_sizes, int n_in,
                              void* d_out, int out_size) {
    const float* q    = (const float*)d_in[0];
    const float* k    = (const float*)d_in[1];
    const float* v    = (const float*)d_in[2];
    const float* wq_w = (const float*)d_in[3];
    const float* wq_b = (const float*)d_in[4];
    const float* wk_w = (const float*)d_in[5];
    const float* wk_b = (const float*)d_in[6];
    const float* wv_w = (const float*)d_in[7];
    const float* wv_b = (const float*)d_in[8];
    const float* wo_w = (const float*)d_in[9];
    const float* wo_b = (const float*)d_in[10];
    float* out = (float*)d_out;

    float *Qp, *Kp, *Vp, *Cp;
    cudaGetSymbolAddress((void**)&Qp, g_q);
    cudaGetSymbolAddress((void**)&Kp, g_k);
    cudaGetSymbolAddress((void**)&Vp, g_v);
    cudaGetSymbolAddress((void**)&Cp, g_ctx);

    const int M = BB * LL;  // 8192

    GemmArgs aq{q, wq_w, wq_b, Qp, 1};
    GemmArgs ak{k, wk_w, wk_b, Kp, 1};
    GemmArgs av{v, wv_w, wv_b, Vp, 1};
    GemmArgs ao{Cp, wo_w, wo_b, out, 0};

    dim3 gq(DD / 128, M / 128, 3);  // (8, 64, 3) fused QKV
    gemm_v2_kernel<<<gq, 128>>>(aq, ak, av, M, DD, DD);

    dim3 ga(LL / 128, HH, BB);  // (16, 16, 4)
    attn_v2_kernel<<<ga, 128>>>(Qp, Kp, Vp, Cp);

    dim3 go(DD / 128, M / 128, 1);  // (8, 64)
    gemm_v2_kernel<<<go, 128>>>(ao, ao, ao, M, DD, DD);
}

// round 13
// speedup vs baseline: 4.0299x; 1.0609x over previous
#include <cuda_runtime.h>
#include <cstdint>

#define BB 4
#define LL 2048
#define DD 1024
#define HH 16
#define DK 64

// Scratch buffers (allocation-free rule: __device__ globals)
__device__ float g_q[BB * LL * DD];
__device__ float g_k[BB * LL * DD];
__device__ float g_v[BB * LL * DD];
__device__ float g_ctx[BB * LL * DD];
// tf32-exact copies of inputs/weights
__device__ float g_rq[BB * LL * DD];
__device__ float g_rk[BB * LL * DD];
__device__ float g_rv[BB * LL * DD];
__device__ float g_rw[4 * DD * DD];

__device__ __forceinline__ uint32_t f2tf(float x) {
    uint32_t u;
    asm("cvt.rna.tf32.f32 %0, %1;" : "=r"(u) : "f"(x));
    return u;
}

__device__ __forceinline__ void mma_tf32(float& d0, float& d1, float& d2, float& d3,
                                         uint32_t a0, uint32_t a1, uint32_t a2, uint32_t a3,
                                         uint32_t b0, uint32_t b1) {
    asm volatile(
        "mma.sync.aligned.m16n8k8.row.col.f32.tf32.tf32.f32 "
        "{%0,%1,%2,%3}, {%4,%5,%6,%7}, {%8,%9}, {%0,%1,%2,%3};"
        : "+f"(d0), "+f"(d1), "+f"(d2), "+f"(d3)
        : "r"(a0), "r"(a1), "r"(a2), "r"(a3), "r"(b0), "r"(b1));
}

__device__ __forceinline__ void cpasync16(uint32_t s, const void* g) {
    asm volatile("cp.async.cg.shared.global [%0], [%1], 16;" :: "r"(s), "l"(g) : "memory");
}
__device__ __forceinline__ void cp_commit() {
    asm volatile("cp.async.commit_group;" ::: "memory");
}
template <int N>
__device__ __forceinline__ void cp_wait() {
    asm volatile("cp.async.wait_group %0;" :: "n"(N) : "memory");
}
__device__ __forceinline__ uint32_t smem_u32(const void* p) {
    uint32_t a;
    asm("{ .reg .u64 t; cvta.to.shared.u64 t, %1; cvt.u32.u64 %0, t; }"
        : "=r"(a) : "l"(p));
    return a;
}

__device__ __forceinline__ int swz(int row) { return (row ^ (row >> 2)) & 3; }

// ============================================================
// Pre-round kernels: copy buffers with cvt.rna.tf32
// ============================================================
struct RoundPair { const float4* in; float4* out; };

__global__ void round4_kernel(RoundPair p0, RoundPair p1, RoundPair p2, RoundPair p3,
                              int n4) {
    RoundPair p = (blockIdx.z == 0) ? p0 : (blockIdx.z == 1) ? p1
                : (blockIdx.z == 2) ? p2 : p3;
    for (int i = blockIdx.x * blockDim.x + threadIdx.x; i < n4;
         i += gridDim.x * blockDim.x) {
        float4 v = p.in[i];
        v.x = __uint_as_float(f2tf(v.x));
        v.y = __uint_as_float(f2tf(v.y));
        v.z = __uint_as_float(f2tf(v.z));
        v.w = __uint_as_float(f2tf(v.w));
        p.out[i] = v;
    }
}

// ============================================================
// GEMM v3: C[M,N] = A[M,K] @ W[N,K]^T + bias[N]
// A and W must be tf32-exact in gmem.
// 256 threads (8 warps, 2x4), warp tile 64x32, CTA 128x128, BK=16.
// cp.async 4-stage pipeline. Smem layout per stage:
//   A: 128 rows x 16 floats, float4-slot j of row r stored at slot j^swz(r)
//   B: same. Fragment loads are conflict-free LDS.32.
// ============================================================
#define GST 4
#define STG_FLOATS 4096        // (128*16)*2 per stage
#define GSMEM_BYTES (GST * STG_FLOATS * 4)   // 65536

struct GemmArgs {
    const float* A;
    const float* W;
    const float* bias;
    float* C;
    int round_out;
};

__global__ __launch_bounds__(256, 2)
void gemm_v3_kernel(GemmArgs ga0, GemmArgs ga1, GemmArgs ga2,
                    int M, int N, int K) {
    extern __shared__ float dsm[];
    GemmArgs ga = (blockIdx.z == 0) ? ga0 : (blockIdx.z == 1) ? ga1 : ga2;

    const int tid  = threadIdx.x;
    const int warp = tid >> 5;
    const int lane = tid & 31;
    const int wm = warp >> 2;         // 0..1
    const int wn = warp & 3;          // 0..3
    const int g  = lane >> 2;
    const int t  = lane & 3;
    const int m0 = wm * 64;
    const int n0 = wn * 32;

    const int bm = blockIdx.y;
    const int bn = blockIdx.x;

    const float* Ab = ga.A + (size_t)(bm * 128) * K;
    const float* Wb = ga.W + (size_t)(bn * 128) * K;

    const uint32_t sbase = smem_u32(dsm);

    // cp.async mapping: 2 A-chunks + 2 B-chunks per thread per stage
    const int r_ld = tid >> 2;        // rows r_ld and r_ld+64
    const int j_ld = tid & 3;

#define LOAD_STAGE(st_)                                                            \
    do {                                                                           \
        const int buf_ = (st_) & (GST - 1);                                        \
        const uint32_t sa_ = sbase + buf_ * (STG_FLOATS * 4);                      \
        const uint32_t sb_ = sa_ + 2048 * 4;                                       \
        const size_t ko_ = (size_t)(st_) * 16 + j_ld * 4;                          \
        _Pragma("unroll")                                                          \
        for (int rep = 0; rep < 2; rep++) {                                        \
            const int row = r_ld + rep * 64;                                       \
            const uint32_t so = (uint32_t)(row * 16 + ((j_ld ^ swz(row)) << 2)) * 4;\
            cpasync16(sa_ + so, Ab + (size_t)row * K + ko_);                       \
            cpasync16(sb_ + so, Wb + (size_t)row * K + ko_);                       \
        }                                                                          \
    } while (0)

    float acc[4][4][4];
#pragma unroll
    for (int i = 0; i < 4; i++)
#pragma unroll
        for (int j = 0; j < 4; j++)
#pragma unroll
            for (int r = 0; r < 4; r++) acc[i][j][r] = 0.0f;

    const int NIT = K >> 4;   // 64

    // prologue: 3 stages in flight
#pragma unroll
    for (int s = 0; s < GST - 1; s++) {
        LOAD_STAGE(s);
        cp_commit();
    }

    for (int kt = 0; kt < NIT; kt++) {
        cp_wait<GST - 2>();
        __syncthreads();

        const int nx = kt + GST - 1;
        if (nx < NIT) LOAD_STAGE(nx);
        cp_commit();

        const float* SA = dsm + (kt & (GST - 1)) * STG_FLOATS;
        const float* SB = SA + 2048;

        // fragment loads (conflict-free LDS.32)
        uint32_t af[4][4], af2[4][4], bf[4][2], bf2[4][2];
#pragma unroll
        for (int mt = 0; mt < 4; mt++) {
            const int rlo = m0 + mt * 16 + g;
            const int rhi = rlo + 8;
            const int slo = swz(rlo), shi = swz(rhi);
            af[mt][0]  = __float_as_uint(SA[rlo * 16 + ((0 ^ slo) << 2) + t]);
            af[mt][1]  = __float_as_uint(SA[rhi * 16 + ((0 ^ shi) << 2) + t]);
            af[mt][2]  = __float_as_uint(SA[rlo * 16 + ((1 ^ slo) << 2) + t]);
            af[mt][3]  = __float_as_uint(SA[rhi * 16 + ((1 ^ shi) << 2) + t]);
            af2[mt][0] = __float_as_uint(SA[rlo * 16 + ((2 ^ slo) << 2) + t]);
            af2[mt][1] = __float_as_uint(SA[rhi * 16 + ((2 ^ shi) << 2) + t]);
            af2[mt][2] = __float_as_uint(SA[rlo * 16 + ((3 ^ slo) << 2) + t]);
            af2[mt][3] = __float_as_uint(SA[rhi * 16 + ((3 ^ shi) << 2) + t]);
        }
#pragma unroll
        for (int nt = 0; nt < 4; nt++) {
            const int rb = n0 + nt * 8 + g;
            const int sb = swz(rb);
            bf[nt][0]  = __float_as_uint(SB[rb * 16 + ((0 ^ sb) << 2) + t]);
            bf[nt][1]  = __float_as_uint(SB[rb * 16 + ((1 ^ sb) << 2) + t]);
            bf2[nt][0] = __float_as_uint(SB[rb * 16 + ((2 ^ sb) << 2) + t]);
            bf2[nt][1] = __float_as_uint(SB[rb * 16 + ((3 ^ sb) << 2) + t]);
        }

#pragma unroll
        for (int mt = 0; mt < 4; mt++)
#pragma unroll
            for (int nt = 0; nt < 4; nt++)
                mma_tf32(acc[mt][nt][0], acc[mt][nt][1], acc[mt][nt][2], acc[mt][nt][3],
                         af[mt][0], af[mt][1], af[mt][2], af[mt][3],
                         bf[nt][0], bf[nt][1]);
#pragma unroll
        for (int mt = 0; mt < 4; mt++)
#pragma unroll
            for (int nt = 0; nt < 4; nt++)
                mma_tf32(acc[mt][nt][0], acc[mt][nt][1], acc[mt][nt][2], acc[mt][nt][3],
                         af2[mt][0], af2[mt][1], af2[mt][2], af2[mt][3],
                         bf2[nt][0], bf2[nt][1]);
        __syncthreads();
    }
#undef LOAD_STAGE

    // epilogue: bias + float2 stores
#pragma unroll
    for (int mt = 0; mt < 4; mt++) {
        const int row0 = bm * 128 + m0 + mt * 16 + g;
#pragma unroll
        for (int nt = 0; nt < 4; nt++) {
            const int col = bn * 128 + n0 + nt * 8 + 2 * t;
            const float b0 = ga.bias[col];
            const float b1 = ga.bias[col + 1];
            float2 v0 = make_float2(acc[mt][nt][0] + b0, acc[mt][nt][1] + b1);
            float2 v1 = make_float2(acc[mt][nt][2] + b0, acc[mt][nt][3] + b1);
            if (ga.round_out) {
                v0.x = __uint_as_float(f2tf(v0.x)); v0.y = __uint_as_float(f2tf(v0.y));
                v1.x = __uint_as_float(f2tf(v1.x)); v1.y = __uint_as_float(f2tf(v1.y));
            }
            *(float2*)(ga.C + (size_t)row0 * N + col)       = v0;
            *(float2*)(ga.C + (size_t)(row0 + 8) * N + col) = v1;
        }
    }
}

// ============================================================
// Attention v2 (unchanged except: epilogue rounds ctx to tf32
// so the WO GEMM can consume it via cp.async).
// ============================================================
__global__ __launch_bounds__(128, 2)
void attn_v2_kernel(const float* __restrict__ Q,
                    const float* __restrict__ K,
                    const float* __restrict__ V,
                    float* __restrict__ ctx) {
    __shared__ float Ks[64 * 64];
    __shared__ float Vt[64 * 64];

    const int tid  = threadIdx.x;
    const int warp = tid >> 5;
    const int lane = tid & 31;
    const int g = lane >> 2;
    const int t = lane & 3;

    const int qt = (int)gridDim.x - 1 - (int)blockIdx.x;
    const int h  = blockIdx.y;
    const int b  = blockIdx.z;

    const int q0 = qt * 128;
    int rA[2], rB[2];
#pragma unroll
    for (int mt = 0; mt < 2; mt++) {
        rA[mt] = q0 + warp * 32 + mt * 16 + g;
        rB[mt] = rA[mt] + 8;
    }

    uint32_t qa[2][8][4];
#pragma unroll
    for (int mt = 0; mt < 2; mt++) {
        const float* qAp = Q + (size_t)(b * LL + rA[mt]) * DD + h * DK;
        const float* qBp = Q + (size_t)(b * LL + rB[mt]) * DD + h * DK;
#pragma unroll
        for (int ks = 0; ks < 8; ks++) {
            qa[mt][ks][0] = __float_as_uint(qAp[ks * 8 + t] * 0.125f);
            qa[mt][ks][1] = __float_as_uint(qBp[ks * 8 + t] * 0.125f);
            qa[mt][ks][2] = __float_as_uint(qAp[ks * 8 + t + 4] * 0.125f);
            qa[mt][ks][3] = __float_as_uint(qBp[ks * 8 + t + 4] * 0.125f);
        }
    }

    float o[2][8][4];
#pragma unroll
    for (int mt = 0; mt < 2; mt++)
#pragma unroll
        for (int nd = 0; nd < 8; nd++)
#pragma unroll
            for (int r = 0; r < 4; r++) o[mt][nd][r] = 0.0f;
    float mA[2] = {-1e30f, -1e30f}, mB[2] = {-1e30f, -1e30f};
    float lA[2] = {0.0f, 0.0f},    lB[2] = {0.0f, 0.0f};

    const int ntiles = 2 * qt + 2;

    for (int tt = 0; tt < ntiles; tt++) {
        const int k0 = tt * 64;
        __syncthreads();
#pragma unroll
        for (int j = 0; j < 8; j++) {
            const int i = tid + j * 128;
            const int r  = i >> 4;
            const int c4 = i & 15;
            const size_t goff = (size_t)(b * LL + k0 + r) * DD + h * DK + c4 * 4;
            float4 kv = *(const float4*)(K + goff);
            float4 vv = *(const float4*)(V + goff);
            {
                const int sw = swz(r);
                float* kd = &Ks[r * 64 + (((c4 >> 2) + r) & 3) * 16 + (c4 & 3)];
                kd[((0 ^ sw) << 2)] = kv.x;
                kd[((1 ^ sw) << 2)] = kv.y;
                kd[((2 ^ sw) << 2)] = kv.z;
                kd[((3 ^ sw) << 2)] = kv.w;
            }
            {
                const int kch = r >> 4;
                const int kc  = r & 15;
                float vals[4] = {vv.x, vv.y, vv.z, vv.w};
#pragma unroll
                for (int e = 0; e < 4; e++) {
                    const int rd = c4 * 4 + e;
                    const int swd = swz(rd);
                    Vt[rd * 64 + ((kch + rd) & 3) * 16 +
                       (((kc & 3) ^ swd) << 2) + (kc >> 2)] = vals[e];
                }
            }
        }
        __syncthreads();

        float s[2][8][4];
#pragma unroll
        for (int mt = 0; mt < 2; mt++)
#pragma unroll
            for (int nt = 0; nt < 8; nt++)
#pragma unroll
                for (int r = 0; r < 4; r++) s[mt][nt][r] = 0.0f;

#pragma unroll
        for (int ch = 0; ch < 4; ch++) {
            float4 bf[8];
#pragma unroll
            for (int nt = 0; nt < 8; nt++) {
                const int rk = nt * 8 + g;
                bf[nt] = *(const float4*)&Ks[rk * 64 + ((ch + rk) & 3) * 16 +
                                             ((t ^ swz(rk)) << 2)];
            }
#pragma unroll
            for (int mt = 0; mt < 2; mt++)
#pragma unroll
                for (int nt = 0; nt < 8; nt++) {
                    mma_tf32(s[mt][nt][0], s[mt][nt][1], s[mt][nt][2], s[mt][nt][3],
                             qa[mt][2 * ch][0], qa[mt][2 * ch][1],
                             qa[mt][2 * ch][2], qa[mt][2 * ch][3],
                             __float_as_uint(bf[nt].x), __float_as_uint(bf[nt].y));
                    mma_tf32(s[mt][nt][0], s[mt][nt][1], s[mt][nt][2], s[mt][nt][3],
                             qa[mt][2 * ch + 1][0], qa[mt][2 * ch + 1][1],
                             qa[mt][2 * ch + 1][2], qa[mt][2 * ch + 1][3],
                             __float_as_uint(bf[nt].z), __float_as_uint(bf[nt].w));
                }
        }

        if (tt >= 2 * qt) {
#pragma unroll
            for (int mt = 0; mt < 2; mt++)
#pragma unroll
                for (int nt = 0; nt < 8; nt++) {
                    int col = k0 + nt * 8 + 2 * t;
                    if (col     > rA[mt]) s[mt][nt][0] = -1e30f;
                    if (col + 1 > rA[mt]) s[mt][nt][1] = -1e30f;
                    if (col     > rB[mt]) s[mt][nt][2] = -1e30f;
                    if (col + 1 > rB[mt]) s[mt][nt][3] = -1e30f;
                }
        }

#pragma unroll
        for (int mt = 0; mt < 2; mt++) {
            float mx0 = -1e30f, mx1 = -1e30f;
#pragma unroll
            for (int nt = 0; nt < 8; nt++) {
                mx0 = fmaxf(mx0, fmaxf(s[mt][nt][0], s[mt][nt][1]));
                mx1 = fmaxf(mx1, fmaxf(s[mt][nt][2], s[mt][nt][3]));
            }
            mx0 = fmaxf(mx0, __shfl_xor_sync(0xffffffffu, mx0, 1));
            mx0 = fmaxf(mx0, __shfl_xor_sync(0xffffffffu, mx0, 2));
            mx1 = fmaxf(mx1, __shfl_xor_sync(0xffffffffu, mx1, 1));
            mx1 = fmaxf(mx1, __shfl_xor_sync(0xffffffffu, mx1, 2));

            float mn0 = fmaxf(mA[mt], mx0), mn1 = fmaxf(mB[mt], mx1);
            float cr0 = __expf(mA[mt] - mn0), cr1 = __expf(mB[mt] - mn1);
            mA[mt] = mn0; mB[mt] = mn1;
            lA[mt] *= cr0; lB[mt] *= cr1;
#pragma unroll
            for (int nd = 0; nd < 8; nd++) {
                o[mt][nd][0] *= cr0; o[mt][nd][1] *= cr0;
                o[mt][nd][2] *= cr1; o[mt][nd][3] *= cr1;
            }

            float s0 = 0.0f, s1 = 0.0f;
#pragma unroll
            for (int nt = 0; nt < 8; nt++) {
                s[mt][nt][0] = __expf(s[mt][nt][0] - mn0);
                s[mt][nt][1] = __expf(s[mt][nt][1] - mn0);
                s[mt][nt][2] = __expf(s[mt][nt][2] - mn1);
                s[mt][nt][3] = __expf(s[mt][nt][3] - mn1);
                s0 += s[mt][nt][0] + s[mt][nt][1];
                s1 += s[mt][nt][2] + s[mt][nt][3];
            }
            s0 += __shfl_xor_sync(0xffffffffu, s0, 1);
            s0 += __shfl_xor_sync(0xffffffffu, s0, 2);
            s1 += __shfl_xor_sync(0xffffffffu, s1, 1);
            s1 += __shfl_xor_sync(0xffffffffu, s1, 2);
            lA[mt] += s0; lB[mt] += s1;
        }

        const int src1 = (lane & 28) | (t >> 1);
#pragma unroll
        for (int ch = 0; ch < 4; ch++) {
            float4 bf[8];
#pragma unroll
            for (int nd = 0; nd < 8; nd++) {
                const int rd = nd * 8 + g;
                bf[nd] = *(const float4*)&Vt[rd * 64 + ((ch + rd) & 3) * 16 +
                                             ((t ^ swz(rd)) << 2)];
            }
#pragma unroll
            for (int mt = 0; mt < 2; mt++)
#pragma unroll
                for (int kh = 0; kh < 2; kh++) {
                    const int ks = 2 * ch + kh;
                    uint32_t u0 = f2tf(s[mt][ks][0]), u1 = f2tf(s[mt][ks][1]);
                    uint32_t u2 = f2tf(s[mt][ks][2]), u3 = f2tf(s[mt][ks][3]);
                    uint32_t x0 = __shfl_sync(0xffffffffu, u0, src1);
                    uint32_t x1 = __shfl_sync(0xffffffffu, u1, src1);
                    uint32_t x2 = __shfl_sync(0xffffffffu, u2, src1);
                    uint32_t x3 = __shfl_sync(0xffffffffu, u3, src1);
                    uint32_t y0 = __shfl_sync(0xffffffffu, u0, src1 + 2);
                    uint32_t y1 = __shfl_sync(0xffffffffu, u1, src1 + 2);
                    uint32_t y2 = __shfl_sync(0xffffffffu, u2, src1 + 2);
                    uint32_t y3 = __shfl_sync(0xffffffffu, u3, src1 + 2);
                    uint32_t a0 = (t & 1) ? x1 : x0;
                    uint32_t a1 = (t & 1) ? x3 : x2;
                    uint32_t a2 = (t & 1) ? y1 : y0;
                    uint32_t a3 = (t & 1) ? y3 : y2;
#pragma unroll
                    for (int nd = 0; nd < 8; nd++) {
                        uint32_t b0 = kh ? __float_as_uint(bf[nd].z)
                                         : __float_as_uint(bf[nd].x);
                        uint32_t b1 = kh ? __float_as_uint(bf[nd].w)
                                         : __float_as_uint(bf[nd].y);
                        mma_tf32(o[mt][nd][0], o[mt][nd][1], o[mt][nd][2], o[mt][nd][3],
                                 a0, a1, a2, a3, b0, b1);
                    }
                }
        }
    }

#pragma unroll
    for (int mt = 0; mt < 2; mt++) {
        const float i0 = 1.0f / lA[mt], i1 = 1.0f / lB[mt];
#pragma unroll
        for (int nd = 0; nd < 8; nd++) {
            const int col = h * DK + nd * 8 + 2 * t;
            float2 vA, vB;
            vA.x = __uint_as_float(f2tf(o[mt][nd][0] * i0));
            vA.y = __uint_as_float(f2tf(o[mt][nd][1] * i0));
            vB.x = __uint_as_float(f2tf(o[mt][nd][2] * i1));
            vB.y = __uint_as_float(f2tf(o[mt][nd][3] * i1));
            *(float2*)(ctx + (size_t)(b * LL + rA[mt]) * DD + col) = vA;
            *(float2*)(ctx + (size_t)(b * LL + rB[mt]) * DD + col) = vB;
        }
    }
}

// ============================================================
// Launch
// ============================================================
extern "C" void kernel_launch(void* const* d_in, const int* in_sizes, int n_in,
                              void* d_out, int out_size) {
    const float* q    = (const float*)d_in[0];
    const float* k    = (const float*)d_in[1];
    const float* v    = (const float*)d_in[2];
    const float* wq_w = (const float*)d_in[3];
    const float* wq_b = (const float*)d_in[4];
    const float* wk_w = (const float*)d_in[5];
    const float* wk_b = (const float*)d_in[6];
    const float* wv_w = (const float*)d_in[7];
    const float* wv_b = (const float*)d_in[8];
    const float* wo_w = (const float*)d_in[9];
    const float* wo_b = (const float*)d_in[10];
    float* out = (float*)d_out;

    float *Qp, *Kp, *Vp, *Cp, *Rq, *Rk, *Rv, *Rw;
    cudaGetSymbolAddress((void**)&Qp, g_q);
    cudaGetSymbolAddress((void**)&Kp, g_k);
    cudaGetSymbolAddress((void**)&Vp, g_v);
    cudaGetSymbolAddress((void**)&Cp, g_ctx);
    cudaGetSymbolAddress((void**)&Rq, g_rq);
    cudaGetSymbolAddress((void**)&Rk, g_rk);
    cudaGetSymbolAddress((void**)&Rv, g_rv);
    cudaGetSymbolAddress((void**)&Rw, g_rw);

    static int attr_set = 0;
    if (!attr_set) {
        cudaFuncSetAttribute(gemm_v3_kernel,
                             cudaFuncAttributeMaxDynamicSharedMemorySize, GSMEM_BYTES);
        attr_set = 1;
    }

    const int M = BB * LL;  // 8192

    // pre-round q/k/v and weights to tf32
    {
        const int n4_in = BB * LL * DD / 4;   // 2097152
        RoundPair pq{(const float4*)q, (float4*)Rq};
        RoundPair pk{(const float4*)k, (float4*)Rk};
        RoundPair pv{(const float4*)v, (float4*)Rv};
        round4_kernel<<<dim3(512, 1, 3), 256>>>(pq, pk, pv, pq, n4_in);

        const int n4_w = DD * DD / 4;         // 262144
        RoundPair w0{(const float4*)wq_w, (float4*)(Rw + 0 * DD * DD)};
        RoundPair w1{(const float4*)wk_w, (float4*)(Rw + 1 * DD * DD)};
        RoundPair w2{(const float4*)wv_w, (float4*)(Rw + 2 * DD * DD)};
        RoundPair w3{(const float4*)wo_w, (float4*)(Rw + 3 * DD * DD)};
        round4_kernel<<<dim3(256, 1, 4), 256>>>(w0, w1, w2, w3, n4_w);
    }

    GemmArgs aq{Rq, Rw + 0 * DD * DD, wq_b, Qp, 1};
    GemmArgs ak{Rk, Rw + 1 * DD * DD, wk_b, Kp, 1};
    GemmArgs av{Rv, Rw + 2 * DD * DD, wv_b, Vp, 1};
    GemmArgs ao{Cp, Rw + 3 * DD * DD, wo_b, out, 0};

    dim3 gq(DD / 128, M / 128, 3);  // (8, 64, 3) fused QKV
    gemm_v3_kernel<<<gq, 256, GSMEM_BYTES>>>(aq, ak, av, M, DD, DD);

    dim3 ga(LL / 128, HH, BB);  // (16, 16, 4)
    attn_v2_kernel<<<ga, 128>>>(Qp, Kp, Vp, Cp);

    dim3 go(DD / 128, M / 128, 1);  // (8, 64)
    gemm_v3_kernel<<<go, 256, GSMEM_BYTES>>>(ao, ao, ao, M, DD, DD);
}